// round 1
// baseline (speedup 1.0000x reference)
#include <cuda_runtime.h>
#include <math.h>

#define B_   2
#define T_   2048
#define D_   1024
#define H_   16
#define HKV_ 4
#define HD_  64
#define G_   4

// Scratch (static device globals — no allocation in kernel_launch)
__device__ float g_q[(size_t)B_ * T_ * H_ * HD_];
__device__ float g_k[(size_t)B_ * T_ * HKV_ * HD_];
__device__ float g_v[(size_t)B_ * T_ * HKV_ * HD_];
__device__ float g_o[(size_t)B_ * T_ * H_ * HD_];

// ---------------------------------------------------------------------------
// SGEMM NT: C[M,N] = A[M,K] @ B[N,K]^T   (both row-major, K contiguous)
// 128x128 tile, TK=8, 256 threads, 8x8 per thread.
// ---------------------------------------------------------------------------
#define TM 128
#define TN 128
#define TK 8

__global__ __launch_bounds__(256) void sgemm_nt(
    const float* __restrict__ A, const float* __restrict__ B,
    float* __restrict__ C, int M, int N, int K)
{
    __shared__ float As[TK][TM + 4];   // pitch 132: STS conflict-free, 16B-aligned reads
    __shared__ float Bs[TK][TN + 4];

    const int m0 = blockIdx.y * TM;
    const int n0 = blockIdx.x * TN;
    const int t  = threadIdx.x;

    const int lr = t >> 1;            // tile row 0..127
    const int lc = (t & 1) * 4;       // k offset 0 or 4
    const int ty = t >> 4;            // 0..15
    const int tx = t & 15;            // 0..15

    float acc[8][8];
#pragma unroll
    for (int i = 0; i < 8; i++)
#pragma unroll
        for (int j = 0; j < 8; j++) acc[i][j] = 0.f;

    for (int k0 = 0; k0 < K; k0 += TK) {
        float4 a4 = *(const float4*)(A + (size_t)(m0 + lr) * K + k0 + lc);
        As[lc + 0][lr] = a4.x; As[lc + 1][lr] = a4.y;
        As[lc + 2][lr] = a4.z; As[lc + 3][lr] = a4.w;
        float4 b4 = *(const float4*)(B + (size_t)(n0 + lr) * K + k0 + lc);
        Bs[lc + 0][lr] = b4.x; Bs[lc + 1][lr] = b4.y;
        Bs[lc + 2][lr] = b4.z; Bs[lc + 3][lr] = b4.w;
        __syncthreads();

#pragma unroll
        for (int kk = 0; kk < TK; kk++) {
            float4 a0 = *(float4*)&As[kk][ty * 8];
            float4 a1 = *(float4*)&As[kk][ty * 8 + 4];
            float4 b0 = *(float4*)&Bs[kk][tx * 8];
            float4 b1 = *(float4*)&Bs[kk][tx * 8 + 4];
            float ar[8] = {a0.x, a0.y, a0.z, a0.w, a1.x, a1.y, a1.z, a1.w};
            float br[8] = {b0.x, b0.y, b0.z, b0.w, b1.x, b1.y, b1.z, b1.w};
#pragma unroll
            for (int i = 0; i < 8; i++)
#pragma unroll
                for (int j = 0; j < 8; j++)
                    acc[i][j] = fmaf(ar[i], br[j], acc[i][j]);
        }
        __syncthreads();
    }

#pragma unroll
    for (int i = 0; i < 8; i++) {
        float* crow = C + (size_t)(m0 + ty * 8 + i) * N + n0 + tx * 8;
        float4 c0 = make_float4(acc[i][0], acc[i][1], acc[i][2], acc[i][3]);
        float4 c1 = make_float4(acc[i][4], acc[i][5], acc[i][6], acc[i][7]);
        *(float4*)(crow)     = c0;
        *(float4*)(crow + 4) = c1;
    }
}

// ---------------------------------------------------------------------------
// RoPE (half-split) on q and k; q also scaled by q_gain[h] * 1/sqrt(HD).
// ---------------------------------------------------------------------------
__global__ void rope_kernel(const float* __restrict__ q_gain)
{
    const int total_q = B_ * T_ * H_ * (HD_ / 2);      // 2^21
    const int total_k = B_ * T_ * HKV_ * (HD_ / 2);    // 2^19
    int idx = blockIdx.x * blockDim.x + threadIdx.x;
    if (idx >= total_q + total_k) return;

    const float LN = logf(10000.0f);
    if (idx < total_q) {
        int j = idx & 31;
        int h = (idx >> 5) & 15;
        int t = (idx >> 9) & 2047;
        int b = idx >> 20;
        float invf = expf(-LN * ((float)(2 * j) / (float)HD_));
        float f = (float)t * invf;
        float c = cosf(f), s = sinf(f);
        float* base = g_q + ((((size_t)b * T_ + t) * H_ + h) * HD_);
        float x1 = base[j], x2 = base[j + 32];
        float gain = q_gain[h] * 0.125f;   // q_gain * 1/sqrt(64)
        base[j]      = (x1 * c - x2 * s) * gain;
        base[j + 32] = (x1 * s + x2 * c) * gain;
    } else {
        int i2 = idx - total_q;
        int j  = i2 & 31;
        int kv = (i2 >> 5) & 3;
        int t  = (i2 >> 7) & 2047;
        int b  = i2 >> 18;
        float invf = expf(-LN * ((float)(2 * j) / (float)HD_));
        float f = (float)t * invf;
        float c = cosf(f), s = sinf(f);
        float* base = g_k + ((((size_t)b * T_ + t) * HKV_ + kv) * HD_);
        float x1 = base[j], x2 = base[j + 32];
        base[j]      = x1 * c - x2 * s;
        base[j + 32] = x1 * s + x2 * c;
    }
}

// ---------------------------------------------------------------------------
// Flash attention (causal, GQA). One block = 128 q rows of one (b, h).
// One thread per q row; K/V tiles of BN=32 in SMEM (broadcast reads).
// Raw scores parked in SMEM Ps[j][tid] (avoids dyn-indexed register array).
// ---------------------------------------------------------------------------
#define BN 32
#define FBM 128

__global__ __launch_bounds__(FBM) void flash_kernel()
{
    __shared__ float Ks[BN][HD_];
    __shared__ float Vs[BN][HD_];
    __shared__ float Ps[BN][FBM];

    const int qt  = blockIdx.x;
    const int h   = blockIdx.y;
    const int b   = blockIdx.z;
    const int tid = threadIdx.x;
    const int qi  = qt * FBM + tid;
    const int kvh = h >> 2;   // h / G

    float qreg[HD_];
    const float* qrow = g_q + ((((size_t)b * T_ + qi) * H_ + h) * HD_);
#pragma unroll
    for (int d4 = 0; d4 < 16; d4++) {
        float4 t4 = *(const float4*)(qrow + d4 * 4);
        qreg[d4 * 4 + 0] = t4.x; qreg[d4 * 4 + 1] = t4.y;
        qreg[d4 * 4 + 2] = t4.z; qreg[d4 * 4 + 3] = t4.w;
    }

    float o_acc[HD_];
#pragma unroll
    for (int d = 0; d < HD_; d++) o_acc[d] = 0.f;
    float m = -1e30f, l = 0.f;

    const int s_end = (qt + 1) * FBM;
    for (int s0 = 0; s0 < s_end; s0 += BN) {
        // cooperative K/V tile load (float4, coalesced within rows)
        for (int i = tid; i < BN * (HD_ / 4); i += FBM) {
            int row = i >> 4;
            int c   = (i & 15) << 2;
            size_t kbase = (((size_t)b * T_ + (s0 + row)) * HKV_ + kvh) * HD_ + c;
            *(float4*)&Ks[row][c] = *(const float4*)(g_k + kbase);
            *(float4*)&Vs[row][c] = *(const float4*)(g_v + kbase);
        }
        __syncthreads();

        if (qi >= s0) {
            float tmax = -1e30f;
#pragma unroll 4
            for (int j = 0; j < BN; j++) {
                float acc = 0.f;
#pragma unroll
                for (int d4 = 0; d4 < 16; d4++) {
                    float4 k4 = *(float4*)&Ks[j][d4 * 4];
                    acc = fmaf(qreg[d4 * 4 + 0], k4.x, acc);
                    acc = fmaf(qreg[d4 * 4 + 1], k4.y, acc);
                    acc = fmaf(qreg[d4 * 4 + 2], k4.z, acc);
                    acc = fmaf(qreg[d4 * 4 + 3], k4.w, acc);
                }
                acc = (s0 + j <= qi) ? acc : -1e30f;   // causal mask
                Ps[j][tid] = acc;
                tmax = fmaxf(tmax, acc);
            }

            float m_new = fmaxf(m, tmax);
            float corr  = __expf(m - m_new);
            l *= corr;
#pragma unroll
            for (int d = 0; d < HD_; d++) o_acc[d] *= corr;

#pragma unroll 2
            for (int j = 0; j < BN; j++) {
                float p = __expf(Ps[j][tid] - m_new);
                l += p;
#pragma unroll
                for (int d4 = 0; d4 < 16; d4++) {
                    float4 v4 = *(float4*)&Vs[j][d4 * 4];
                    o_acc[d4 * 4 + 0] = fmaf(p, v4.x, o_acc[d4 * 4 + 0]);
                    o_acc[d4 * 4 + 1] = fmaf(p, v4.y, o_acc[d4 * 4 + 1]);
                    o_acc[d4 * 4 + 2] = fmaf(p, v4.z, o_acc[d4 * 4 + 2]);
                    o_acc[d4 * 4 + 3] = fmaf(p, v4.w, o_acc[d4 * 4 + 3]);
                }
            }
            m = m_new;
        }
        __syncthreads();
    }

    float inv_l = 1.0f / l;
    float* orow = g_o + ((((size_t)b * T_ + qi) * H_ + h) * HD_);
#pragma unroll
    for (int d4 = 0; d4 < 16; d4++) {
        float4 r;
        r.x = o_acc[d4 * 4 + 0] * inv_l;
        r.y = o_acc[d4 * 4 + 1] * inv_l;
        r.z = o_acc[d4 * 4 + 2] * inv_l;
        r.w = o_acc[d4 * 4 + 3] * inv_l;
        *(float4*)(orow + d4 * 4) = r;
    }
}

// ---------------------------------------------------------------------------
// Launch
// ---------------------------------------------------------------------------
extern "C" void kernel_launch(void* const* d_in, const int* in_sizes, int n_in,
                              void* d_out, int out_size)
{
    (void)in_sizes; (void)n_in; (void)out_size;
    const float* x      = (const float*)d_in[0];
    const float* Wq     = (const float*)d_in[1];
    const float* Wk     = (const float*)d_in[2];
    const float* Wv     = (const float*)d_in[3];
    const float* Wp     = (const float*)d_in[4];
    const float* q_gain = (const float*)d_in[5];
    float* out = (float*)d_out;

    float *qb, *kb, *vb, *ob;
    cudaGetSymbolAddress((void**)&qb, g_q);
    cudaGetSymbolAddress((void**)&kb, g_k);
    cudaGetSymbolAddress((void**)&vb, g_v);
    cudaGetSymbolAddress((void**)&ob, g_o);

    const int M = B_ * T_;   // 4096

    // QKV projections
    sgemm_nt<<<dim3(D_ / TN, M / TM), 256>>>(x, Wq, qb, M, D_, D_);
    sgemm_nt<<<dim3((HKV_ * HD_) / TN, M / TM), 256>>>(x, Wk, kb, M, HKV_ * HD_, D_);
    sgemm_nt<<<dim3((HKV_ * HD_) / TN, M / TM), 256>>>(x, Wv, vb, M, HKV_ * HD_, D_);

    // RoPE + gain/scale
    const int total = B_ * T_ * (H_ + HKV_) * (HD_ / 2);
    rope_kernel<<<(total + 255) / 256, 256>>>(q_gain);

    // Causal flash attention
    flash_kernel<<<dim3(T_ / FBM, H_, B_), FBM>>>();

    // Output projection
    sgemm_nt<<<dim3(D_ / TN, M / TM), 256>>>(ob, Wp, out, M, D_, D_);
}

// round 2
// speedup vs baseline: 1.3782x; 1.3782x over previous
#include <cuda_runtime.h>
#include <math.h>
#include <stdint.h>

#define B_   2
#define T_   2048
#define D_   1024
#define H_   16
#define HKV_ 4
#define HD_  64
#define G_   4

// Scratch (static device globals — no allocation in kernel_launch)
__device__ float g_q[(size_t)B_ * T_ * H_ * HD_];
__device__ float g_k[(size_t)B_ * T_ * HKV_ * HD_];
__device__ float g_v[(size_t)B_ * T_ * HKV_ * HD_];
__device__ float g_o[(size_t)B_ * T_ * H_ * HD_];

// ---------------------------------------------------------------------------
// TF32 tensor-core GEMM NT: C[M,N] = A[M,K] @ B[N,K]^T (row-major, K contig)
// 128x128 block tile, K-chunk 16, 256 threads (8 warps, 2m x 4n),
// warp tile 64x32 via mma.sync.m16n8k8.tf32, double-buffered SMEM.
// SMEM pitch 20 floats -> conflict-free fragment LDS.
// ---------------------------------------------------------------------------
#define GP 20

__device__ __forceinline__ float to_tf32(float x) {
    float r;
    asm("cvt.rna.tf32.f32 %0, %1;" : "=f"(r) : "f"(x));
    return r;
}

__device__ __forceinline__ void mma_tf32(float* d, const uint32_t* a, const uint32_t* b) {
    asm volatile(
        "mma.sync.aligned.m16n8k8.row.col.f32.tf32.tf32.f32 "
        "{%0,%1,%2,%3}, {%4,%5,%6,%7}, {%8,%9}, {%0,%1,%2,%3};"
        : "+f"(d[0]), "+f"(d[1]), "+f"(d[2]), "+f"(d[3])
        : "r"(a[0]), "r"(a[1]), "r"(a[2]), "r"(a[3]), "r"(b[0]), "r"(b[1]));
}

__global__ __launch_bounds__(256) void gemm_tf32_nt(
    const float* __restrict__ A, const float* __restrict__ B,
    float* __restrict__ C, int M, int N, int K)
{
    __shared__ float As[2][128][GP];
    __shared__ float Bs[2][128][GP];

    const int m0   = blockIdx.y * 128;
    const int n0   = blockIdx.x * 128;
    const int t    = threadIdx.x;
    const int lane = t & 31;
    const int wid  = t >> 5;
    const int wm   = (wid >> 2) * 64;   // warp m offset (0 or 64)
    const int wn   = (wid & 3) * 32;    // warp n offset

    // global->smem mapping: thread loads 2 float4 of row (t>>1), k group (t&1)*8
    const int lr = t >> 1;
    const int kg = (t & 1) * 8;

    float acc[4][4][4];
#pragma unroll
    for (int i = 0; i < 4; i++)
#pragma unroll
        for (int j = 0; j < 4; j++)
#pragma unroll
            for (int r = 0; r < 4; r++) acc[i][j][r] = 0.f;

    const float* Aptr = A + (size_t)(m0 + lr) * K + kg;
    const float* Bptr = B + (size_t)(n0 + lr) * K + kg;

    float4 ra0 = *(const float4*)(Aptr);
    float4 ra1 = *(const float4*)(Aptr + 4);
    float4 rb0 = *(const float4*)(Bptr);
    float4 rb1 = *(const float4*)(Bptr + 4);
    Aptr += 16; Bptr += 16;

    // STS chunk 0 (tf32-rounded)
    {
        float4 ca0 = make_float4(to_tf32(ra0.x), to_tf32(ra0.y), to_tf32(ra0.z), to_tf32(ra0.w));
        float4 ca1 = make_float4(to_tf32(ra1.x), to_tf32(ra1.y), to_tf32(ra1.z), to_tf32(ra1.w));
        float4 cb0 = make_float4(to_tf32(rb0.x), to_tf32(rb0.y), to_tf32(rb0.z), to_tf32(rb0.w));
        float4 cb1 = make_float4(to_tf32(rb1.x), to_tf32(rb1.y), to_tf32(rb1.z), to_tf32(rb1.w));
        *(float4*)&As[0][lr][kg]     = ca0;
        *(float4*)&As[0][lr][kg + 4] = ca1;
        *(float4*)&Bs[0][lr][kg]     = cb0;
        *(float4*)&Bs[0][lr][kg + 4] = cb1;
    }
    __syncthreads();

    const int nk = K / 16;
    // preload chunk 1
    if (nk > 1) {
        ra0 = *(const float4*)(Aptr); ra1 = *(const float4*)(Aptr + 4);
        rb0 = *(const float4*)(Bptr); rb1 = *(const float4*)(Bptr + 4);
        Aptr += 16; Bptr += 16;
    }

    for (int it = 0; it < nk; it++) {
        const int cur = it & 1;
        if (it + 1 < nk) {
            // STS next chunk (buffer last read at it-1; safe after that sync)
            const int nxt = (it + 1) & 1;
            float4 ca0 = make_float4(to_tf32(ra0.x), to_tf32(ra0.y), to_tf32(ra0.z), to_tf32(ra0.w));
            float4 ca1 = make_float4(to_tf32(ra1.x), to_tf32(ra1.y), to_tf32(ra1.z), to_tf32(ra1.w));
            float4 cb0 = make_float4(to_tf32(rb0.x), to_tf32(rb0.y), to_tf32(rb0.z), to_tf32(rb0.w));
            float4 cb1 = make_float4(to_tf32(rb1.x), to_tf32(rb1.y), to_tf32(rb1.z), to_tf32(rb1.w));
            *(float4*)&As[nxt][lr][kg]     = ca0;
            *(float4*)&As[nxt][lr][kg + 4] = ca1;
            *(float4*)&Bs[nxt][lr][kg]     = cb0;
            *(float4*)&Bs[nxt][lr][kg + 4] = cb1;
            if (it + 2 < nk) {
                ra0 = *(const float4*)(Aptr); ra1 = *(const float4*)(Aptr + 4);
                rb0 = *(const float4*)(Bptr); rb1 = *(const float4*)(Bptr + 4);
                Aptr += 16; Bptr += 16;
            }
        }

#pragma unroll
        for (int ks = 0; ks < 16; ks += 8) {
            uint32_t af[4][4], bf[4][2];
            const int c = ks + (lane & 3);
#pragma unroll
            for (int mf = 0; mf < 4; mf++) {
                const int r = wm + mf * 16 + (lane >> 2);
                af[mf][0] = __float_as_uint(As[cur][r][c]);
                af[mf][1] = __float_as_uint(As[cur][r + 8][c]);
                af[mf][2] = __float_as_uint(As[cur][r][c + 4]);
                af[mf][3] = __float_as_uint(As[cur][r + 8][c + 4]);
            }
#pragma unroll
            for (int nf = 0; nf < 4; nf++) {
                const int r = wn + nf * 8 + (lane >> 2);
                bf[nf][0] = __float_as_uint(Bs[cur][r][c]);
                bf[nf][1] = __float_as_uint(Bs[cur][r][c + 4]);
            }
#pragma unroll
            for (int mf = 0; mf < 4; mf++)
#pragma unroll
                for (int nf = 0; nf < 4; nf++)
                    mma_tf32(acc[mf][nf], af[mf], bf[nf]);
        }
        __syncthreads();
    }

    // epilogue: c0,c1 at (row, col..col+1); c2,c3 at (row+8, ...)
#pragma unroll
    for (int mf = 0; mf < 4; mf++) {
#pragma unroll
        for (int nf = 0; nf < 4; nf++) {
            const int row = m0 + wm + mf * 16 + (lane >> 2);
            const int col = n0 + wn + nf * 8 + (lane & 3) * 2;
            float2 v0 = make_float2(acc[mf][nf][0], acc[mf][nf][1]);
            float2 v1 = make_float2(acc[mf][nf][2], acc[mf][nf][3]);
            *(float2*)(C + (size_t)row * N + col)       = v0;
            *(float2*)(C + (size_t)(row + 8) * N + col) = v1;
        }
    }
}

// ---------------------------------------------------------------------------
// RoPE (half-split) on q and k; q also scaled by q_gain[h] * 1/sqrt(HD).
// ---------------------------------------------------------------------------
__global__ void rope_kernel(const float* __restrict__ q_gain)
{
    const int total_q = B_ * T_ * H_ * (HD_ / 2);
    const int total_k = B_ * T_ * HKV_ * (HD_ / 2);
    int idx = blockIdx.x * blockDim.x + threadIdx.x;
    if (idx >= total_q + total_k) return;

    const float LN = logf(10000.0f);
    if (idx < total_q) {
        int j = idx & 31;
        int h = (idx >> 5) & 15;
        int t = (idx >> 9) & 2047;
        int b = idx >> 20;
        float invf = expf(-LN * ((float)(2 * j) / (float)HD_));
        float f = (float)t * invf;
        float c = cosf(f), s = sinf(f);
        float* base = g_q + ((((size_t)b * T_ + t) * H_ + h) * HD_);
        float x1 = base[j], x2 = base[j + 32];
        float gain = q_gain[h] * 0.125f;
        base[j]      = (x1 * c - x2 * s) * gain;
        base[j + 32] = (x1 * s + x2 * c) * gain;
    } else {
        int i2 = idx - total_q;
        int j  = i2 & 31;
        int kv = (i2 >> 5) & 3;
        int t  = (i2 >> 7) & 2047;
        int b  = i2 >> 18;
        float invf = expf(-LN * ((float)(2 * j) / (float)HD_));
        float f = (float)t * invf;
        float c = cosf(f), s = sinf(f);
        float* base = g_k + ((((size_t)b * T_ + t) * HKV_ + kv) * HD_);
        float x1 = base[j], x2 = base[j + 32];
        base[j]      = x1 * c - x2 * s;
        base[j + 32] = x1 * s + x2 * c;
    }
}

// ---------------------------------------------------------------------------
// Flash attention (causal, GQA). One block = 128 q rows of one (b, h).
// ---------------------------------------------------------------------------
#define BN 32
#define FBM 128

__global__ __launch_bounds__(FBM) void flash_kernel()
{
    __shared__ float Ks[BN][HD_];
    __shared__ float Vs[BN][HD_];
    __shared__ float Ps[BN][FBM];

    const int qt  = blockIdx.x;
    const int h   = blockIdx.y;
    const int b   = blockIdx.z;
    const int tid = threadIdx.x;
    const int qi  = qt * FBM + tid;
    const int kvh = h >> 2;

    float qreg[HD_];
    const float* qrow = g_q + ((((size_t)b * T_ + qi) * H_ + h) * HD_);
#pragma unroll
    for (int d4 = 0; d4 < 16; d4++) {
        float4 t4 = *(const float4*)(qrow + d4 * 4);
        qreg[d4 * 4 + 0] = t4.x; qreg[d4 * 4 + 1] = t4.y;
        qreg[d4 * 4 + 2] = t4.z; qreg[d4 * 4 + 3] = t4.w;
    }

    float o_acc[HD_];
#pragma unroll
    for (int d = 0; d < HD_; d++) o_acc[d] = 0.f;
    float m = -1e30f, l = 0.f;

    const int s_end = (qt + 1) * FBM;
    for (int s0 = 0; s0 < s_end; s0 += BN) {
        for (int i = tid; i < BN * (HD_ / 4); i += FBM) {
            int row = i >> 4;
            int c   = (i & 15) << 2;
            size_t kbase = (((size_t)b * T_ + (s0 + row)) * HKV_ + kvh) * HD_ + c;
            *(float4*)&Ks[row][c] = *(const float4*)(g_k + kbase);
            *(float4*)&Vs[row][c] = *(const float4*)(g_v + kbase);
        }
        __syncthreads();

        if (qi >= s0) {
            float tmax = -1e30f;
#pragma unroll 4
            for (int j = 0; j < BN; j++) {
                float acc = 0.f;
#pragma unroll
                for (int d4 = 0; d4 < 16; d4++) {
                    float4 k4 = *(float4*)&Ks[j][d4 * 4];
                    acc = fmaf(qreg[d4 * 4 + 0], k4.x, acc);
                    acc = fmaf(qreg[d4 * 4 + 1], k4.y, acc);
                    acc = fmaf(qreg[d4 * 4 + 2], k4.z, acc);
                    acc = fmaf(qreg[d4 * 4 + 3], k4.w, acc);
                }
                acc = (s0 + j <= qi) ? acc : -1e30f;
                Ps[j][tid] = acc;
                tmax = fmaxf(tmax, acc);
            }

            float m_new = fmaxf(m, tmax);
            float corr  = __expf(m - m_new);
            l *= corr;
#pragma unroll
            for (int d = 0; d < HD_; d++) o_acc[d] *= corr;

#pragma unroll 2
            for (int j = 0; j < BN; j++) {
                float p = __expf(Ps[j][tid] - m_new);
                l += p;
#pragma unroll
                for (int d4 = 0; d4 < 16; d4++) {
                    float4 v4 = *(float4*)&Vs[j][d4 * 4];
                    o_acc[d4 * 4 + 0] = fmaf(p, v4.x, o_acc[d4 * 4 + 0]);
                    o_acc[d4 * 4 + 1] = fmaf(p, v4.y, o_acc[d4 * 4 + 1]);
                    o_acc[d4 * 4 + 2] = fmaf(p, v4.z, o_acc[d4 * 4 + 2]);
                    o_acc[d4 * 4 + 3] = fmaf(p, v4.w, o_acc[d4 * 4 + 3]);
                }
            }
            m = m_new;
        }
        __syncthreads();
    }

    float inv_l = 1.0f / l;
    float* orow = g_o + ((((size_t)b * T_ + qi) * H_ + h) * HD_);
#pragma unroll
    for (int d4 = 0; d4 < 16; d4++) {
        float4 r;
        r.x = o_acc[d4 * 4 + 0] * inv_l;
        r.y = o_acc[d4 * 4 + 1] * inv_l;
        r.z = o_acc[d4 * 4 + 2] * inv_l;
        r.w = o_acc[d4 * 4 + 3] * inv_l;
        *(float4*)(orow + d4 * 4) = r;
    }
}

// ---------------------------------------------------------------------------
// Launch
// ---------------------------------------------------------------------------
extern "C" void kernel_launch(void* const* d_in, const int* in_sizes, int n_in,
                              void* d_out, int out_size)
{
    (void)in_sizes; (void)n_in; (void)out_size;
    const float* x      = (const float*)d_in[0];
    const float* Wq     = (const float*)d_in[1];
    const float* Wk     = (const float*)d_in[2];
    const float* Wv     = (const float*)d_in[3];
    const float* Wp     = (const float*)d_in[4];
    const float* q_gain = (const float*)d_in[5];
    float* out = (float*)d_out;

    float *qb, *kb, *vb, *ob;
    cudaGetSymbolAddress((void**)&qb, g_q);
    cudaGetSymbolAddress((void**)&kb, g_k);
    cudaGetSymbolAddress((void**)&vb, g_v);
    cudaGetSymbolAddress((void**)&ob, g_o);

    const int M = B_ * T_;   // 4096

    // QKV projections (tf32 tensor cores)
    gemm_tf32_nt<<<dim3(D_ / 128, M / 128), 256>>>(x, Wq, qb, M, D_, D_);
    gemm_tf32_nt<<<dim3((HKV_ * HD_) / 128, M / 128), 256>>>(x, Wk, kb, M, HKV_ * HD_, D_);
    gemm_tf32_nt<<<dim3((HKV_ * HD_) / 128, M / 128), 256>>>(x, Wv, vb, M, HKV_ * HD_, D_);

    // RoPE + gain/scale
    const int total = B_ * T_ * (H_ + HKV_) * (HD_ / 2);
    rope_kernel<<<(total + 255) / 256, 256>>>(q_gain);

    // Causal flash attention
    flash_kernel<<<dim3(T_ / FBM, H_, B_), FBM>>>();

    // Output projection
    gemm_tf32_nt<<<dim3(D_ / 128, M / 128), 256>>>(ob, Wp, out, M, D_, D_);
}

// round 3
// speedup vs baseline: 3.3310x; 2.4168x over previous
#include <cuda_runtime.h>
#include <math.h>
#include <stdint.h>

#define B_   2
#define T_   2048
#define D_   1024
#define H_   16
#define HKV_ 4
#define HD_  64
#define G_   4

#define QKVD 1536      // fused qkv row width: 1024 q | 256 k | 256 v
#define KOFF 1024
#define VOFF 1280

// Scratch (static device globals — no allocation in kernel_launch)
__device__ float g_qkv[(size_t)B_ * T_ * QKVD];
__device__ float g_o[(size_t)B_ * T_ * D_];

__device__ __forceinline__ float to_tf32(float x) {
    float r;
    asm("cvt.rna.tf32.f32 %0, %1;" : "=f"(r) : "f"(x));
    return r;
}

__device__ __forceinline__ void mma_tf32(float* d, const uint32_t* a, const uint32_t* b) {
    asm volatile(
        "mma.sync.aligned.m16n8k8.row.col.f32.tf32.tf32.f32 "
        "{%0,%1,%2,%3}, {%4,%5,%6,%7}, {%8,%9}, {%0,%1,%2,%3};"
        : "+f"(d[0]), "+f"(d[1]), "+f"(d[2]), "+f"(d[3])
        : "r"(a[0]), "r"(a[1]), "r"(a[2]), "r"(a[3]), "r"(b[0]), "r"(b[1]));
}

// ---------------------------------------------------------------------------
// TF32 GEMM NT core (128x128 tile, K-chunk 16, 8 warps 2m x 4n, dbl-buffered)
// ---------------------------------------------------------------------------
#define GP 20

__global__ __launch_bounds__(256) void gemm_tf32_nt(
    const float* __restrict__ A, const float* __restrict__ B,
    float* __restrict__ C, int M, int N, int K)
{
    __shared__ float As[2][128][GP];
    __shared__ float Bs[2][128][GP];

    const int m0   = blockIdx.y * 128;
    const int n0   = blockIdx.x * 128;
    const int t    = threadIdx.x;
    const int lane = t & 31;
    const int wid  = t >> 5;
    const int wm   = (wid >> 2) * 64;
    const int wn   = (wid & 3) * 32;
    const int lr = t >> 1;
    const int kg = (t & 1) * 8;

    float acc[4][4][4];
#pragma unroll
    for (int i = 0; i < 4; i++)
#pragma unroll
        for (int j = 0; j < 4; j++)
#pragma unroll
            for (int r = 0; r < 4; r++) acc[i][j][r] = 0.f;

    const float* Aptr = A + (size_t)(m0 + lr) * K + kg;
    const float* Bptr = B + (size_t)(n0 + lr) * K + kg;

    float4 ra0 = *(const float4*)(Aptr);
    float4 ra1 = *(const float4*)(Aptr + 4);
    float4 rb0 = *(const float4*)(Bptr);
    float4 rb1 = *(const float4*)(Bptr + 4);
    Aptr += 16; Bptr += 16;

    *(float4*)&As[0][lr][kg]     = make_float4(to_tf32(ra0.x), to_tf32(ra0.y), to_tf32(ra0.z), to_tf32(ra0.w));
    *(float4*)&As[0][lr][kg + 4] = make_float4(to_tf32(ra1.x), to_tf32(ra1.y), to_tf32(ra1.z), to_tf32(ra1.w));
    *(float4*)&Bs[0][lr][kg]     = make_float4(to_tf32(rb0.x), to_tf32(rb0.y), to_tf32(rb0.z), to_tf32(rb0.w));
    *(float4*)&Bs[0][lr][kg + 4] = make_float4(to_tf32(rb1.x), to_tf32(rb1.y), to_tf32(rb1.z), to_tf32(rb1.w));
    __syncthreads();

    const int nk = K / 16;
    if (nk > 1) {
        ra0 = *(const float4*)(Aptr); ra1 = *(const float4*)(Aptr + 4);
        rb0 = *(const float4*)(Bptr); rb1 = *(const float4*)(Bptr + 4);
        Aptr += 16; Bptr += 16;
    }

    for (int it = 0; it < nk; it++) {
        const int cur = it & 1;
        if (it + 1 < nk) {
            const int nxt = (it + 1) & 1;
            *(float4*)&As[nxt][lr][kg]     = make_float4(to_tf32(ra0.x), to_tf32(ra0.y), to_tf32(ra0.z), to_tf32(ra0.w));
            *(float4*)&As[nxt][lr][kg + 4] = make_float4(to_tf32(ra1.x), to_tf32(ra1.y), to_tf32(ra1.z), to_tf32(ra1.w));
            *(float4*)&Bs[nxt][lr][kg]     = make_float4(to_tf32(rb0.x), to_tf32(rb0.y), to_tf32(rb0.z), to_tf32(rb0.w));
            *(float4*)&Bs[nxt][lr][kg + 4] = make_float4(to_tf32(rb1.x), to_tf32(rb1.y), to_tf32(rb1.z), to_tf32(rb1.w));
            if (it + 2 < nk) {
                ra0 = *(const float4*)(Aptr); ra1 = *(const float4*)(Aptr + 4);
                rb0 = *(const float4*)(Bptr); rb1 = *(const float4*)(Bptr + 4);
                Aptr += 16; Bptr += 16;
            }
        }

#pragma unroll
        for (int ks = 0; ks < 16; ks += 8) {
            uint32_t af[4][4], bf[4][2];
            const int c = ks + (lane & 3);
#pragma unroll
            for (int mf = 0; mf < 4; mf++) {
                const int r = wm + mf * 16 + (lane >> 2);
                af[mf][0] = __float_as_uint(As[cur][r][c]);
                af[mf][1] = __float_as_uint(As[cur][r + 8][c]);
                af[mf][2] = __float_as_uint(As[cur][r][c + 4]);
                af[mf][3] = __float_as_uint(As[cur][r + 8][c + 4]);
            }
#pragma unroll
            for (int nf = 0; nf < 4; nf++) {
                const int r = wn + nf * 8 + (lane >> 2);
                bf[nf][0] = __float_as_uint(Bs[cur][r][c]);
                bf[nf][1] = __float_as_uint(Bs[cur][r][c + 4]);
            }
#pragma unroll
            for (int mf = 0; mf < 4; mf++)
#pragma unroll
                for (int nf = 0; nf < 4; nf++)
                    mma_tf32(acc[mf][nf], af[mf], bf[nf]);
        }
        __syncthreads();
    }

#pragma unroll
    for (int mf = 0; mf < 4; mf++) {
#pragma unroll
        for (int nf = 0; nf < 4; nf++) {
            const int row = m0 + wm + mf * 16 + (lane >> 2);
            const int col = n0 + wn + nf * 8 + (lane & 3) * 2;
            *(float2*)(C + (size_t)row * N + col)       = make_float2(acc[mf][nf][0], acc[mf][nf][1]);
            *(float2*)(C + (size_t)(row + 8) * N + col) = make_float2(acc[mf][nf][2], acc[mf][nf][3]);
        }
    }
}

// ---------------------------------------------------------------------------
// Fused QKV GEMM: C[M][1536] = x @ [Wq|Wk|Wv]^T. Per-block weight select.
// ---------------------------------------------------------------------------
__global__ __launch_bounds__(256) void gemm_qkv(
    const float* __restrict__ A, const float* __restrict__ Wq,
    const float* __restrict__ Wk, const float* __restrict__ Wv,
    float* __restrict__ C, int M, int K)
{
    const int N = QKVD;
    __shared__ float As[2][128][GP];
    __shared__ float Bs[2][128][GP];

    const int m0   = blockIdx.y * 128;
    const int n0   = blockIdx.x * 128;
    const int t    = threadIdx.x;
    const int lane = t & 31;
    const int wid  = t >> 5;
    const int wm   = (wid >> 2) * 64;
    const int wn   = (wid & 3) * 32;
    const int lr = t >> 1;
    const int kg = (t & 1) * 8;

    const float* Bsel; int nbase;
    if (n0 < KOFF)      { Bsel = Wq; nbase = n0; }
    else if (n0 < VOFF) { Bsel = Wk; nbase = n0 - KOFF; }
    else                { Bsel = Wv; nbase = n0 - VOFF; }

    float acc[4][4][4];
#pragma unroll
    for (int i = 0; i < 4; i++)
#pragma unroll
        for (int j = 0; j < 4; j++)
#pragma unroll
            for (int r = 0; r < 4; r++) acc[i][j][r] = 0.f;

    const float* Aptr = A + (size_t)(m0 + lr) * K + kg;
    const float* Bptr = Bsel + (size_t)(nbase + lr) * K + kg;

    float4 ra0 = *(const float4*)(Aptr);
    float4 ra1 = *(const float4*)(Aptr + 4);
    float4 rb0 = *(const float4*)(Bptr);
    float4 rb1 = *(const float4*)(Bptr + 4);
    Aptr += 16; Bptr += 16;

    *(float4*)&As[0][lr][kg]     = make_float4(to_tf32(ra0.x), to_tf32(ra0.y), to_tf32(ra0.z), to_tf32(ra0.w));
    *(float4*)&As[0][lr][kg + 4] = make_float4(to_tf32(ra1.x), to_tf32(ra1.y), to_tf32(ra1.z), to_tf32(ra1.w));
    *(float4*)&Bs[0][lr][kg]     = make_float4(to_tf32(rb0.x), to_tf32(rb0.y), to_tf32(rb0.z), to_tf32(rb0.w));
    *(float4*)&Bs[0][lr][kg + 4] = make_float4(to_tf32(rb1.x), to_tf32(rb1.y), to_tf32(rb1.z), to_tf32(rb1.w));
    __syncthreads();

    const int nk = K / 16;
    if (nk > 1) {
        ra0 = *(const float4*)(Aptr); ra1 = *(const float4*)(Aptr + 4);
        rb0 = *(const float4*)(Bptr); rb1 = *(const float4*)(Bptr + 4);
        Aptr += 16; Bptr += 16;
    }

    for (int it = 0; it < nk; it++) {
        const int cur = it & 1;
        if (it + 1 < nk) {
            const int nxt = (it + 1) & 1;
            *(float4*)&As[nxt][lr][kg]     = make_float4(to_tf32(ra0.x), to_tf32(ra0.y), to_tf32(ra0.z), to_tf32(ra0.w));
            *(float4*)&As[nxt][lr][kg + 4] = make_float4(to_tf32(ra1.x), to_tf32(ra1.y), to_tf32(ra1.z), to_tf32(ra1.w));
            *(float4*)&Bs[nxt][lr][kg]     = make_float4(to_tf32(rb0.x), to_tf32(rb0.y), to_tf32(rb0.z), to_tf32(rb0.w));
            *(float4*)&Bs[nxt][lr][kg + 4] = make_float4(to_tf32(rb1.x), to_tf32(rb1.y), to_tf32(rb1.z), to_tf32(rb1.w));
            if (it + 2 < nk) {
                ra0 = *(const float4*)(Aptr); ra1 = *(const float4*)(Aptr + 4);
                rb0 = *(const float4*)(Bptr); rb1 = *(const float4*)(Bptr + 4);
                Aptr += 16; Bptr += 16;
            }
        }

#pragma unroll
        for (int ks = 0; ks < 16; ks += 8) {
            uint32_t af[4][4], bf[4][2];
            const int c = ks + (lane & 3);
#pragma unroll
            for (int mf = 0; mf < 4; mf++) {
                const int r = wm + mf * 16 + (lane >> 2);
                af[mf][0] = __float_as_uint(As[cur][r][c]);
                af[mf][1] = __float_as_uint(As[cur][r + 8][c]);
                af[mf][2] = __float_as_uint(As[cur][r][c + 4]);
                af[mf][3] = __float_as_uint(As[cur][r + 8][c + 4]);
            }
#pragma unroll
            for (int nf = 0; nf < 4; nf++) {
                const int r = wn + nf * 8 + (lane >> 2);
                bf[nf][0] = __float_as_uint(Bs[cur][r][c]);
                bf[nf][1] = __float_as_uint(Bs[cur][r][c + 4]);
            }
#pragma unroll
            for (int mf = 0; mf < 4; mf++)
#pragma unroll
                for (int nf = 0; nf < 4; nf++)
                    mma_tf32(acc[mf][nf], af[mf], bf[nf]);
        }
        __syncthreads();
    }

#pragma unroll
    for (int mf = 0; mf < 4; mf++) {
#pragma unroll
        for (int nf = 0; nf < 4; nf++) {
            const int row = m0 + wm + mf * 16 + (lane >> 2);
            const int col = n0 + wn + nf * 8 + (lane & 3) * 2;
            *(float2*)(C + (size_t)row * N + col)       = make_float2(acc[mf][nf][0], acc[mf][nf][1]);
            *(float2*)(C + (size_t)(row + 8) * N + col) = make_float2(acc[mf][nf][2], acc[mf][nf][3]);
        }
    }
}

// ---------------------------------------------------------------------------
// RoPE in-place on g_qkv; q scaled by q_gain[h] * 1/sqrt(HD).
// ---------------------------------------------------------------------------
__global__ void rope_kernel(const float* __restrict__ q_gain)
{
    const int total_q = B_ * T_ * H_ * (HD_ / 2);
    const int total_k = B_ * T_ * HKV_ * (HD_ / 2);
    int idx = blockIdx.x * blockDim.x + threadIdx.x;
    if (idx >= total_q + total_k) return;

    const float LN = logf(10000.0f);
    if (idx < total_q) {
        int j = idx & 31;
        int h = (idx >> 5) & 15;
        int t = (idx >> 9) & 2047;
        int b = idx >> 20;
        float invf = expf(-LN * ((float)(2 * j) / (float)HD_));
        float f = (float)t * invf;
        float c = cosf(f), s = sinf(f);
        float* base = g_qkv + ((size_t)(b * T_ + t)) * QKVD + h * HD_;
        float x1 = base[j], x2 = base[j + 32];
        float gain = q_gain[h] * 0.125f;
        base[j]      = (x1 * c - x2 * s) * gain;
        base[j + 32] = (x1 * s + x2 * c) * gain;
    } else {
        int i2 = idx - total_q;
        int j  = i2 & 31;
        int kv = (i2 >> 5) & 3;
        int t  = (i2 >> 7) & 2047;
        int b  = i2 >> 18;
        float invf = expf(-LN * ((float)(2 * j) / (float)HD_));
        float f = (float)t * invf;
        float c = cosf(f), s = sinf(f);
        float* base = g_qkv + ((size_t)(b * T_ + t)) * QKVD + KOFF + kv * HD_;
        float x1 = base[j], x2 = base[j + 32];
        base[j]      = x1 * c - x2 * s;
        base[j + 32] = x1 * s + x2 * c;
    }
}

// ---------------------------------------------------------------------------
// Tensor-core flash attention (causal, GQA).
// Block: 256 thr (8 warps), BM=128 q rows (16/warp), BN=64 kv, HD=64.
// SMEM pitch 76 -> conflict-free fragment LDS for K, V, P patterns.
// ---------------------------------------------------------------------------
#define FP 76
#define FLASH_SMEM (256 * FP * 4)   // Ks 64 rows + Vs 64 rows + Ps 128 rows

__global__ __launch_bounds__(256, 1) void flash_tc()
{
    extern __shared__ float sm[];
    float* Ks = sm;                 // [64][FP]
    float* Vs = sm + 64 * FP;       // [64][FP]
    float* Ps = sm + 128 * FP;      // [128][FP]

    const int qt   = (int)gridDim.x - 1 - (int)blockIdx.x;  // heavy blocks first
    const int h    = blockIdx.y;
    const int b    = blockIdx.z;
    const int tid  = threadIdx.x;
    const int lane = tid & 31;
    const int wid  = tid >> 5;
    const int wm   = wid * 16;
    const int kvh  = h >> 2;
    const int r0   = lane >> 2;
    const int c0   = lane & 3;

    // Q fragments in registers (tf32)
    uint32_t qf[8][4];
    {
        const float* q0 = g_qkv + ((size_t)(b * T_ + qt * 128 + wm + r0)) * QKVD + h * HD_;
        const float* q1 = q0 + (size_t)8 * QKVD;
#pragma unroll
        for (int kb = 0; kb < 8; kb++) {
            qf[kb][0] = __float_as_uint(to_tf32(q0[kb * 8 + c0]));
            qf[kb][1] = __float_as_uint(to_tf32(q1[kb * 8 + c0]));
            qf[kb][2] = __float_as_uint(to_tf32(q0[kb * 8 + c0 + 4]));
            qf[kb][3] = __float_as_uint(to_tf32(q1[kb * 8 + c0 + 4]));
        }
    }

    float oacc[8][4];
#pragma unroll
    for (int nf = 0; nf < 8; nf++)
#pragma unroll
        for (int r = 0; r < 4; r++) oacc[nf][r] = 0.f;
    float m0v = -1e30f, m1v = -1e30f, l0 = 0.f, l1 = 0.f;

    const int qi0 = qt * 128 + wm + r0;
    const int qi1 = qi0 + 8;
    const int s_end = (qt + 1) * 128;

    for (int s0 = 0; s0 < s_end; s0 += 64) {
        // cooperative K/V tile load (tf32-converted)
        {
            const int row = tid >> 2;
            const int cg  = (tid & 3) * 16;
            const float* ksrc = g_qkv + ((size_t)(b * T_ + s0 + row)) * QKVD + KOFF + kvh * HD_ + cg;
            const float* vsrc = ksrc + (VOFF - KOFF);
#pragma unroll
            for (int u = 0; u < 4; u++) {
                float4 k4 = *(const float4*)(ksrc + u * 4);
                float4 v4 = *(const float4*)(vsrc + u * 4);
                *(float4*)&Ks[row * FP + cg + u * 4] =
                    make_float4(to_tf32(k4.x), to_tf32(k4.y), to_tf32(k4.z), to_tf32(k4.w));
                *(float4*)&Vs[row * FP + cg + u * 4] =
                    make_float4(to_tf32(v4.x), to_tf32(v4.y), to_tf32(v4.z), to_tf32(v4.w));
            }
        }
        __syncthreads();

        if (s0 <= qt * 128 + wm + 15) {   // warp has at least one unmasked row
            // S = Q @ K^T   (per-warp 16x64)
            float sacc[8][4];
#pragma unroll
            for (int nf = 0; nf < 8; nf++)
#pragma unroll
                for (int r = 0; r < 4; r++) sacc[nf][r] = 0.f;

#pragma unroll
            for (int kb = 0; kb < 8; kb++) {
#pragma unroll
                for (int nf = 0; nf < 8; nf++) {
                    uint32_t bf[2];
                    bf[0] = __float_as_uint(Ks[(nf * 8 + r0) * FP + kb * 8 + c0]);
                    bf[1] = __float_as_uint(Ks[(nf * 8 + r0) * FP + kb * 8 + c0 + 4]);
                    mma_tf32(sacc[nf], qf[kb], bf);
                }
            }

            // causal mask (only near the diagonal)
            if (s0 + 63 > qt * 128 + wm) {
#pragma unroll
                for (int nf = 0; nf < 8; nf++) {
                    int sj = s0 + nf * 8 + 2 * c0;
                    if (sj > qi0)     sacc[nf][0] = -1e30f;
                    if (sj + 1 > qi0) sacc[nf][1] = -1e30f;
                    if (sj > qi1)     sacc[nf][2] = -1e30f;
                    if (sj + 1 > qi1) sacc[nf][3] = -1e30f;
                }
            }

            // row maxes (per-thread over frags, then quad reduce)
            float tm0 = -1e30f, tm1 = -1e30f;
#pragma unroll
            for (int nf = 0; nf < 8; nf++) {
                tm0 = fmaxf(tm0, fmaxf(sacc[nf][0], sacc[nf][1]));
                tm1 = fmaxf(tm1, fmaxf(sacc[nf][2], sacc[nf][3]));
            }
            tm0 = fmaxf(tm0, __shfl_xor_sync(0xffffffff, tm0, 1));
            tm0 = fmaxf(tm0, __shfl_xor_sync(0xffffffff, tm0, 2));
            tm1 = fmaxf(tm1, __shfl_xor_sync(0xffffffff, tm1, 1));
            tm1 = fmaxf(tm1, __shfl_xor_sync(0xffffffff, tm1, 2));

            float mn0 = fmaxf(m0v, tm0), mn1 = fmaxf(m1v, tm1);
            float cor0 = __expf(m0v - mn0), cor1 = __expf(m1v - mn1);

            // exp, tf32-round, store P, partial sums (sum the ROUNDED values)
            float ps0 = 0.f, ps1 = 0.f;
#pragma unroll
            for (int nf = 0; nf < 8; nf++) {
                float p0 = to_tf32(__expf(sacc[nf][0] - mn0));
                float p1 = to_tf32(__expf(sacc[nf][1] - mn0));
                float p2 = to_tf32(__expf(sacc[nf][2] - mn1));
                float p3 = to_tf32(__expf(sacc[nf][3] - mn1));
                ps0 += p0 + p1; ps1 += p2 + p3;
                *(float2*)&Ps[(wm + r0)     * FP + nf * 8 + 2 * c0] = make_float2(p0, p1);
                *(float2*)&Ps[(wm + r0 + 8) * FP + nf * 8 + 2 * c0] = make_float2(p2, p3);
            }
            ps0 += __shfl_xor_sync(0xffffffff, ps0, 1);
            ps0 += __shfl_xor_sync(0xffffffff, ps0, 2);
            ps1 += __shfl_xor_sync(0xffffffff, ps1, 1);
            ps1 += __shfl_xor_sync(0xffffffff, ps1, 2);
            l0 = l0 * cor0 + ps0;
            l1 = l1 * cor1 + ps1;

#pragma unroll
            for (int nf = 0; nf < 8; nf++) {
                oacc[nf][0] *= cor0; oacc[nf][1] *= cor0;
                oacc[nf][2] *= cor1; oacc[nf][3] *= cor1;
            }
            m0v = mn0; m1v = mn1;

            __syncwarp();

            // O += P @ V   (per-warp 16x64, K=64)
#pragma unroll
            for (int kb = 0; kb < 8; kb++) {
                uint32_t af[4];
                af[0] = __float_as_uint(Ps[(wm + r0)     * FP + kb * 8 + c0]);
                af[1] = __float_as_uint(Ps[(wm + r0 + 8) * FP + kb * 8 + c0]);
                af[2] = __float_as_uint(Ps[(wm + r0)     * FP + kb * 8 + c0 + 4]);
                af[3] = __float_as_uint(Ps[(wm + r0 + 8) * FP + kb * 8 + c0 + 4]);
#pragma unroll
                for (int nf = 0; nf < 8; nf++) {
                    uint32_t bf[2];
                    bf[0] = __float_as_uint(Vs[(kb * 8 + c0)     * FP + nf * 8 + r0]);
                    bf[1] = __float_as_uint(Vs[(kb * 8 + c0 + 4) * FP + nf * 8 + r0]);
                    mma_tf32(oacc[nf], af, bf);
                }
            }
        }
        __syncthreads();
    }

    // epilogue: normalize, write O
    float il0 = 1.0f / l0, il1 = 1.0f / l1;
    float* o0 = g_o + ((size_t)(b * T_ + qi0)) * D_ + h * HD_;
    float* o1 = g_o + ((size_t)(b * T_ + qi1)) * D_ + h * HD_;
#pragma unroll
    for (int nf = 0; nf < 8; nf++) {
        *(float2*)(o0 + nf * 8 + 2 * c0) = make_float2(oacc[nf][0] * il0, oacc[nf][1] * il0);
        *(float2*)(o1 + nf * 8 + 2 * c0) = make_float2(oacc[nf][2] * il1, oacc[nf][3] * il1);
    }
}

// ---------------------------------------------------------------------------
// Launch
// ---------------------------------------------------------------------------
extern "C" void kernel_launch(void* const* d_in, const int* in_sizes, int n_in,
                              void* d_out, int out_size)
{
    (void)in_sizes; (void)n_in; (void)out_size;
    const float* x      = (const float*)d_in[0];
    const float* Wq     = (const float*)d_in[1];
    const float* Wk     = (const float*)d_in[2];
    const float* Wv     = (const float*)d_in[3];
    const float* Wp     = (const float*)d_in[4];
    const float* q_gain = (const float*)d_in[5];
    float* out = (float*)d_out;

    float *qkvb, *ob;
    cudaGetSymbolAddress((void**)&qkvb, g_qkv);
    cudaGetSymbolAddress((void**)&ob, g_o);

    cudaFuncSetAttribute(flash_tc, cudaFuncAttributeMaxDynamicSharedMemorySize, FLASH_SMEM);

    const int M = B_ * T_;   // 4096

    // Fused QKV projection
    gemm_qkv<<<dim3(QKVD / 128, M / 128), 256>>>(x, Wq, Wk, Wv, qkvb, M, D_);

    // RoPE + gain/scale (in place)
    const int total = B_ * T_ * (H_ + HKV_) * (HD_ / 2);
    rope_kernel<<<(total + 255) / 256, 256>>>(q_gain);

    // Tensor-core causal flash attention
    flash_tc<<<dim3(T_ / 128, H_, B_), 256, FLASH_SMEM>>>();

    // Output projection
    gemm_tf32_nt<<<dim3(D_ / 128, M / 128), 256>>>(ob, Wp, out, M, D_, D_);
}

// round 4
// speedup vs baseline: 3.8318x; 1.1504x over previous
#include <cuda_runtime.h>
#include <math.h>
#include <stdint.h>

#define B_   2
#define T_   2048
#define D_   1024
#define H_   16
#define HKV_ 4
#define HD_  64
#define G_   4

#define QKVD 1536      // fused qkv row width: 1024 q | 256 k | 256 v
#define KOFF 1024
#define VOFF 1280

// Scratch (static device globals — no allocation in kernel_launch)
__device__ float g_qkv[(size_t)B_ * T_ * QKVD];
__device__ float g_o[(size_t)B_ * T_ * D_];

__device__ __forceinline__ float to_tf32(float x) {
    float r;
    asm("cvt.rna.tf32.f32 %0, %1;" : "=f"(r) : "f"(x));
    return r;
}

__device__ __forceinline__ void mma_tf32(float* d, const uint32_t* a, const uint32_t* b) {
    asm volatile(
        "mma.sync.aligned.m16n8k8.row.col.f32.tf32.tf32.f32 "
        "{%0,%1,%2,%3}, {%4,%5,%6,%7}, {%8,%9}, {%0,%1,%2,%3};"
        : "+f"(d[0]), "+f"(d[1]), "+f"(d[2]), "+f"(d[3])
        : "r"(a[0]), "r"(a[1]), "r"(a[2]), "r"(a[3]), "r"(b[0]), "r"(b[1]));
}

__device__ __forceinline__ uint32_t smem_u32(const void* p) {
    return (uint32_t)__cvta_generic_to_shared(p);
}

__device__ __forceinline__ void ldm_x4(uint32_t* r, uint32_t a) {
    asm volatile("ldmatrix.sync.aligned.m8n8.x4.shared.b16 {%0,%1,%2,%3}, [%4];"
        : "=r"(r[0]), "=r"(r[1]), "=r"(r[2]), "=r"(r[3]) : "r"(a));
}

// ---------------------------------------------------------------------------
// TF32 GEMM NT core (128x128 tile, K-chunk 16, 8 warps 2m x 4n, dbl-buffered)
// ldmatrix fragment loads, 2 CTAs/SM.
// ---------------------------------------------------------------------------
#define GP 20

#define GEMM_BODY(BSEL, NBASE)                                                             \
    __shared__ float As[2][128][GP];                                                       \
    __shared__ float Bs[2][128][GP];                                                       \
    const int m0   = blockIdx.y * 128;                                                     \
    const int t    = threadIdx.x;                                                          \
    const int lane = t & 31;                                                               \
    const int wid  = t >> 5;                                                               \
    const int wm   = (wid >> 2) * 64;                                                      \
    const int wn   = (wid & 3) * 32;                                                       \
    const int lr = t >> 1;                                                                 \
    const int kg = (t & 1) * 8;                                                            \
    const uint32_t As_u = smem_u32(&As[0][0][0]);                                          \
    const uint32_t Bs_u = smem_u32(&Bs[0][0][0]);                                          \
    const int a_off = ((lane & 7) + ((lane >> 3) & 1) * 8) * GP + ((lane >> 4) & 1) * 4;   \
    const int b_off = ((lane & 7) + ((lane >> 4) & 1) * 8) * GP + ((lane >> 3) & 1) * 4;   \
    float acc[4][4][4];                                                                    \
    _Pragma("unroll") for (int i = 0; i < 4; i++)                                          \
    _Pragma("unroll") for (int j = 0; j < 4; j++)                                          \
    _Pragma("unroll") for (int r = 0; r < 4; r++) acc[i][j][r] = 0.f;                      \
    const float* Aptr = A + (size_t)(m0 + lr) * K + kg;                                    \
    const float* Bptr = (BSEL) + (size_t)((NBASE) + lr) * K + kg;                          \
    float4 ra0 = *(const float4*)(Aptr);                                                   \
    float4 ra1 = *(const float4*)(Aptr + 4);                                               \
    float4 rb0 = *(const float4*)(Bptr);                                                   \
    float4 rb1 = *(const float4*)(Bptr + 4);                                               \
    Aptr += 16; Bptr += 16;                                                                \
    *(float4*)&As[0][lr][kg]     = make_float4(to_tf32(ra0.x), to_tf32(ra0.y), to_tf32(ra0.z), to_tf32(ra0.w)); \
    *(float4*)&As[0][lr][kg + 4] = make_float4(to_tf32(ra1.x), to_tf32(ra1.y), to_tf32(ra1.z), to_tf32(ra1.w)); \
    *(float4*)&Bs[0][lr][kg]     = make_float4(to_tf32(rb0.x), to_tf32(rb0.y), to_tf32(rb0.z), to_tf32(rb0.w)); \
    *(float4*)&Bs[0][lr][kg + 4] = make_float4(to_tf32(rb1.x), to_tf32(rb1.y), to_tf32(rb1.z), to_tf32(rb1.w)); \
    __syncthreads();                                                                       \
    const int nk = K / 16;                                                                 \
    if (nk > 1) {                                                                          \
        ra0 = *(const float4*)(Aptr); ra1 = *(const float4*)(Aptr + 4);                    \
        rb0 = *(const float4*)(Bptr); rb1 = *(const float4*)(Bptr + 4);                    \
        Aptr += 16; Bptr += 16;                                                            \
    }                                                                                      \
    for (int it = 0; it < nk; it++) {                                                      \
        const int cur = it & 1;                                                            \
        if (it + 1 < nk) {                                                                 \
            const int nxt = (it + 1) & 1;                                                  \
            *(float4*)&As[nxt][lr][kg]     = make_float4(to_tf32(ra0.x), to_tf32(ra0.y), to_tf32(ra0.z), to_tf32(ra0.w)); \
            *(float4*)&As[nxt][lr][kg + 4] = make_float4(to_tf32(ra1.x), to_tf32(ra1.y), to_tf32(ra1.z), to_tf32(ra1.w)); \
            *(float4*)&Bs[nxt][lr][kg]     = make_float4(to_tf32(rb0.x), to_tf32(rb0.y), to_tf32(rb0.z), to_tf32(rb0.w)); \
            *(float4*)&Bs[nxt][lr][kg + 4] = make_float4(to_tf32(rb1.x), to_tf32(rb1.y), to_tf32(rb1.z), to_tf32(rb1.w)); \
            if (it + 2 < nk) {                                                             \
                ra0 = *(const float4*)(Aptr); ra1 = *(const float4*)(Aptr + 4);            \
                rb0 = *(const float4*)(Bptr); rb1 = *(const float4*)(Bptr + 4);            \
                Aptr += 16; Bptr += 16;                                                    \
            }                                                                              \
        }                                                                                  \
        const uint32_t abuf = As_u + (uint32_t)cur * (128 * GP * 4);                       \
        const uint32_t bbuf = Bs_u + (uint32_t)cur * (128 * GP * 4);                       \
        _Pragma("unroll")                                                                  \
        for (int ks = 0; ks < 16; ks += 8) {                                               \
            uint32_t af[4][4], bf[2][4];                                                   \
            _Pragma("unroll") for (int mf = 0; mf < 4; mf++)                               \
                ldm_x4(af[mf], abuf + 4u * ((wm + mf * 16) * GP + ks + a_off));            \
            _Pragma("unroll") for (int np = 0; np < 2; np++)                               \
                ldm_x4(bf[np], bbuf + 4u * ((wn + np * 16) * GP + ks + b_off));            \
            _Pragma("unroll") for (int mf = 0; mf < 4; mf++)                               \
            _Pragma("unroll") for (int np = 0; np < 2; np++) {                             \
                mma_tf32(acc[mf][np * 2],     af[mf], bf[np]);                             \
                mma_tf32(acc[mf][np * 2 + 1], af[mf], bf[np] + 2);                         \
            }                                                                              \
        }                                                                                  \
        __syncthreads();                                                                   \
    }                                                                                      \
    const int n0 = blockIdx.x * 128;                                                       \
    _Pragma("unroll") for (int mf = 0; mf < 4; mf++)                                       \
    _Pragma("unroll") for (int nf = 0; nf < 4; nf++) {                                     \
        const int row = m0 + wm + mf * 16 + (lane >> 2);                                   \
        const int col = n0 + wn + nf * 8 + (lane & 3) * 2;                                 \
        *(float2*)(C + (size_t)row * N + col)       = make_float2(acc[mf][nf][0], acc[mf][nf][1]); \
        *(float2*)(C + (size_t)(row + 8) * N + col) = make_float2(acc[mf][nf][2], acc[mf][nf][3]); \
    }

__global__ __launch_bounds__(256, 2) void gemm_tf32_nt(
    const float* __restrict__ A, const float* __restrict__ B,
    float* __restrict__ C, int M, int N, int K)
{
    GEMM_BODY(B, blockIdx.x * 128)
}

__global__ __launch_bounds__(256, 2) void gemm_qkv(
    const float* __restrict__ A, const float* __restrict__ Wq,
    const float* __restrict__ Wk, const float* __restrict__ Wv,
    float* __restrict__ C, int M, int K)
{
    const int N = QKVD;
    const int nblk = blockIdx.x * 128;
    const float* Bsel; int nbase;
    if (nblk < KOFF)      { Bsel = Wq; nbase = nblk; }
    else if (nblk < VOFF) { Bsel = Wk; nbase = nblk - KOFF; }
    else                  { Bsel = Wv; nbase = nblk - VOFF; }
    GEMM_BODY(Bsel, nbase)
}

// ---------------------------------------------------------------------------
// RoPE in-place on g_qkv; q scaled by q_gain[h] * 1/sqrt(HD).
// ---------------------------------------------------------------------------
__global__ void rope_kernel(const float* __restrict__ q_gain)
{
    const int total_q = B_ * T_ * H_ * (HD_ / 2);
    const int total_k = B_ * T_ * HKV_ * (HD_ / 2);
    int idx = blockIdx.x * blockDim.x + threadIdx.x;
    if (idx >= total_q + total_k) return;

    const float LN = logf(10000.0f);
    if (idx < total_q) {
        int j = idx & 31;
        int h = (idx >> 5) & 15;
        int t = (idx >> 9) & 2047;
        int b = idx >> 20;
        float invf = expf(-LN * ((float)(2 * j) / (float)HD_));
        float f = (float)t * invf;
        float c = cosf(f), s = sinf(f);
        float* base = g_qkv + ((size_t)(b * T_ + t)) * QKVD + h * HD_;
        float x1 = base[j], x2 = base[j + 32];
        float gain = q_gain[h] * 0.125f;
        base[j]      = (x1 * c - x2 * s) * gain;
        base[j + 32] = (x1 * s + x2 * c) * gain;
    } else {
        int i2 = idx - total_q;
        int j  = i2 & 31;
        int kv = (i2 >> 5) & 3;
        int t  = (i2 >> 7) & 2047;
        int b  = i2 >> 18;
        float invf = expf(-LN * ((float)(2 * j) / (float)HD_));
        float f = (float)t * invf;
        float c = cosf(f), s = sinf(f);
        float* base = g_qkv + ((size_t)(b * T_ + t)) * QKVD + KOFF + kv * HD_;
        float x1 = base[j], x2 = base[j + 32];
        base[j]      = x1 * c - x2 * s;
        base[j + 32] = x1 * s + x2 * c;
    }
}

// ---------------------------------------------------------------------------
// Tensor-core flash attention (causal, GQA), ldmatrix fragment loads.
// Block: 256 thr (8 warps), BM=128 q rows (16/warp), BN=64 kv, HD=64.
// K stored [s][d]; V stored TRANSPOSED [d][s] with 16B-group swizzle;
// P stored [q][s]. Pitch 76 -> conflict-free ldmatrix phases.
// ---------------------------------------------------------------------------
#define FP 76
#define FLASH_SMEM (256 * FP * 4)   // Ks 64 rows + Vt 64 rows + Ps 128 rows

__global__ __launch_bounds__(256, 1) void flash_tc()
{
    extern __shared__ float sm[];
    float* Ks = sm;                 // [64 s][FP]  (cols = d)
    float* Vt = sm + 64 * FP;       // [64 d][FP]  (cols = s, swizzled 16B groups)
    float* Ps = sm + 128 * FP;      // [128 q][FP] (cols = s)

    const int qt   = (int)gridDim.x - 1 - (int)blockIdx.x;  // heavy blocks first
    const int h    = blockIdx.y;
    const int b    = blockIdx.z;
    const int tid  = threadIdx.x;
    const int lane = tid & 31;
    const int wid  = tid >> 5;
    const int wm   = wid * 16;
    const int kvh  = h >> 2;
    const int r0   = lane >> 2;
    const int c0   = lane & 3;

    const uint32_t Ks_u = smem_u32(Ks);
    const uint32_t Vt_u = smem_u32(Vt);
    const uint32_t Ps_u = smem_u32(Ps);

    // ldmatrix per-lane offsets (in floats)
    const int kf_off = (lane & 7) * FP + (lane >> 3) * 4;                       // K/V frag
    const int pa_off = ((lane & 7) + ((lane >> 3) & 1) * 8) * FP + ((lane >> 4) & 1) * 4; // P frag
    const int v_row  = lane & 7;
    const int v_cb   = lane >> 3;

    // Q fragments in registers (tf32)
    uint32_t qf[8][4];
    {
        const float* q0 = g_qkv + ((size_t)(b * T_ + qt * 128 + wm + r0)) * QKVD + h * HD_;
        const float* q1 = q0 + (size_t)8 * QKVD;
#pragma unroll
        for (int kb = 0; kb < 8; kb++) {
            qf[kb][0] = __float_as_uint(to_tf32(q0[kb * 8 + c0]));
            qf[kb][1] = __float_as_uint(to_tf32(q1[kb * 8 + c0]));
            qf[kb][2] = __float_as_uint(to_tf32(q0[kb * 8 + c0 + 4]));
            qf[kb][3] = __float_as_uint(to_tf32(q1[kb * 8 + c0 + 4]));
        }
    }

    float oacc[8][4];
#pragma unroll
    for (int nf = 0; nf < 8; nf++)
#pragma unroll
        for (int r = 0; r < 4; r++) oacc[nf][r] = 0.f;
    float m0v = -1e30f, m1v = -1e30f, l0 = 0.f, l1 = 0.f;

    const int qi0 = qt * 128 + wm + r0;
    const int qi1 = qi0 + 8;
    const int s_end = (qt + 1) * 128;

    for (int s0 = 0; s0 < s_end; s0 += 64) {
        // cooperative K load (row-major) + V transpose-store (swizzled)
        {
            const int row = tid >> 2;            // kv position 0..63
            const int cg  = (tid & 3) * 16;      // d group
            const int swz = tid & 3;             // = (d>>4)&3 for this thread's d range
            const float* ksrc = g_qkv + ((size_t)(b * T_ + s0 + row)) * QKVD + KOFF + kvh * HD_ + cg;
            const float* vsrc = ksrc + (VOFF - KOFF);
#pragma unroll
            for (int u = 0; u < 4; u++) {
                float4 k4 = *(const float4*)(ksrc + u * 4);
                float4 v4 = *(const float4*)(vsrc + u * 4);
                *(float4*)&Ks[row * FP + cg + u * 4] =
                    make_float4(to_tf32(k4.x), to_tf32(k4.y), to_tf32(k4.z), to_tf32(k4.w));
                const int pg = ((row >> 2) ^ swz) * 4 + (row & 3);
                float vv[4] = {v4.x, v4.y, v4.z, v4.w};
#pragma unroll
                for (int e = 0; e < 4; e++)
                    Vt[(cg + u * 4 + e) * FP + pg] = to_tf32(vv[e]);
            }
        }
        __syncthreads();

        if (s0 <= qt * 128 + wm + 15) {   // warp has at least one unmasked row
            // S = Q @ K^T   (per-warp 16x64)
            float sacc[8][4];
#pragma unroll
            for (int nf = 0; nf < 8; nf++)
#pragma unroll
                for (int r = 0; r < 4; r++) sacc[nf][r] = 0.f;

#pragma unroll
            for (int kbp = 0; kbp < 4; kbp++) {
#pragma unroll
                for (int nf = 0; nf < 8; nf++) {
                    uint32_t kb4[4];
                    ldm_x4(kb4, Ks_u + 4u * (nf * 8 * FP + kbp * 16 + kf_off));
                    mma_tf32(sacc[nf], qf[2 * kbp],     kb4);
                    mma_tf32(sacc[nf], qf[2 * kbp + 1], kb4 + 2);
                }
            }

            // causal mask (only near the diagonal)
            if (s0 + 63 > qt * 128 + wm) {
#pragma unroll
                for (int nf = 0; nf < 8; nf++) {
                    int sj = s0 + nf * 8 + 2 * c0;
                    if (sj > qi0)     sacc[nf][0] = -1e30f;
                    if (sj + 1 > qi0) sacc[nf][1] = -1e30f;
                    if (sj > qi1)     sacc[nf][2] = -1e30f;
                    if (sj + 1 > qi1) sacc[nf][3] = -1e30f;
                }
            }

            // row maxes
            float tm0 = -1e30f, tm1 = -1e30f;
#pragma unroll
            for (int nf = 0; nf < 8; nf++) {
                tm0 = fmaxf(tm0, fmaxf(sacc[nf][0], sacc[nf][1]));
                tm1 = fmaxf(tm1, fmaxf(sacc[nf][2], sacc[nf][3]));
            }
            tm0 = fmaxf(tm0, __shfl_xor_sync(0xffffffff, tm0, 1));
            tm0 = fmaxf(tm0, __shfl_xor_sync(0xffffffff, tm0, 2));
            tm1 = fmaxf(tm1, __shfl_xor_sync(0xffffffff, tm1, 1));
            tm1 = fmaxf(tm1, __shfl_xor_sync(0xffffffff, tm1, 2));

            float mn0 = fmaxf(m0v, tm0), mn1 = fmaxf(m1v, tm1);
            float cor0 = __expf(m0v - mn0), cor1 = __expf(m1v - mn1);

            // exp, tf32-round, store P, partial sums (sum the ROUNDED values)
            float ps0 = 0.f, ps1 = 0.f;
#pragma unroll
            for (int nf = 0; nf < 8; nf++) {
                float p0 = to_tf32(__expf(sacc[nf][0] - mn0));
                float p1 = to_tf32(__expf(sacc[nf][1] - mn0));
                float p2 = to_tf32(__expf(sacc[nf][2] - mn1));
                float p3 = to_tf32(__expf(sacc[nf][3] - mn1));
                ps0 += p0 + p1; ps1 += p2 + p3;
                *(float2*)&Ps[(wm + r0)     * FP + nf * 8 + 2 * c0] = make_float2(p0, p1);
                *(float2*)&Ps[(wm + r0 + 8) * FP + nf * 8 + 2 * c0] = make_float2(p2, p3);
            }
            ps0 += __shfl_xor_sync(0xffffffff, ps0, 1);
            ps0 += __shfl_xor_sync(0xffffffff, ps0, 2);
            ps1 += __shfl_xor_sync(0xffffffff, ps1, 1);
            ps1 += __shfl_xor_sync(0xffffffff, ps1, 2);
            l0 = l0 * cor0 + ps0;
            l1 = l1 * cor1 + ps1;

#pragma unroll
            for (int nf = 0; nf < 8; nf++) {
                oacc[nf][0] *= cor0; oacc[nf][1] *= cor0;
                oacc[nf][2] *= cor1; oacc[nf][3] *= cor1;
            }
            m0v = mn0; m1v = mn1;

            __syncwarp();

            // O += P @ V   (per-warp 16x64, K=64) — P and V via ldmatrix
#pragma unroll
            for (int kbp = 0; kbp < 4; kbp++) {
                uint32_t pa0[4], pa1[4];
                ldm_x4(pa0, Ps_u + 4u * (wm * FP + (2 * kbp)     * 8 + pa_off));
                ldm_x4(pa1, Ps_u + 4u * (wm * FP + (2 * kbp + 1) * 8 + pa_off));
#pragma unroll
                for (int nf = 0; nf < 8; nf++) {
                    uint32_t vb[4];
                    const int pg = (kbp * 4 + v_cb) ^ ((nf >> 1) & 3);
                    ldm_x4(vb, Vt_u + 4u * ((nf * 8 + v_row) * FP + pg * 4));
                    mma_tf32(oacc[nf], pa0, vb);
                    mma_tf32(oacc[nf], pa1, vb + 2);
                }
            }
        }
        __syncthreads();
    }

    // epilogue: normalize, write O
    float il0 = 1.0f / l0, il1 = 1.0f / l1;
    float* o0 = g_o + ((size_t)(b * T_ + qi0)) * D_ + h * HD_;
    float* o1 = g_o + ((size_t)(b * T_ + qi1)) * D_ + h * HD_;
#pragma unroll
    for (int nf = 0; nf < 8; nf++) {
        *(float2*)(o0 + nf * 8 + 2 * c0) = make_float2(oacc[nf][0] * il0, oacc[nf][1] * il0);
        *(float2*)(o1 + nf * 8 + 2 * c0) = make_float2(oacc[nf][2] * il1, oacc[nf][3] * il1);
    }
}

// ---------------------------------------------------------------------------
// Launch
// ---------------------------------------------------------------------------
extern "C" void kernel_launch(void* const* d_in, const int* in_sizes, int n_in,
                              void* d_out, int out_size)
{
    (void)in_sizes; (void)n_in; (void)out_size;
    const float* x      = (const float*)d_in[0];
    const float* Wq     = (const float*)d_in[1];
    const float* Wk     = (const float*)d_in[2];
    const float* Wv     = (const float*)d_in[3];
    const float* Wp     = (const float*)d_in[4];
    const float* q_gain = (const float*)d_in[5];
    float* out = (float*)d_out;

    float *qkvb, *ob;
    cudaGetSymbolAddress((void**)&qkvb, g_qkv);
    cudaGetSymbolAddress((void**)&ob, g_o);

    cudaFuncSetAttribute(flash_tc, cudaFuncAttributeMaxDynamicSharedMemorySize, FLASH_SMEM);

    const int M = B_ * T_;   // 4096

    // Fused QKV projection
    gemm_qkv<<<dim3(QKVD / 128, M / 128), 256>>>(x, Wq, Wk, Wv, qkvb, M, D_);

    // RoPE + gain/scale (in place)
    const int total = B_ * T_ * (H_ + HKV_) * (HD_ / 2);
    rope_kernel<<<(total + 255) / 256, 256>>>(q_gain);

    // Tensor-core causal flash attention
    flash_tc<<<dim3(T_ / 128, H_, B_), 256, FLASH_SMEM>>>();

    // Output projection
    gemm_tf32_nt<<<dim3(D_ / 128, M / 128), 256>>>(ob, Wp, out, M, D_, D_);
}

// round 5
// speedup vs baseline: 3.9168x; 1.0222x over previous
#include <cuda_runtime.h>
#include <math.h>
#include <stdint.h>

#define B_   2
#define T_   2048
#define D_   1024
#define H_   16
#define HKV_ 4
#define HD_  64
#define G_   4

#define QKVD 1536      // fused qkv row width: 1024 q | 256 k | 256 v
#define KOFF 1024
#define VOFF 1280

// Scratch (static device globals — no allocation in kernel_launch)
__device__ float g_qkv[(size_t)B_ * T_ * QKVD];
__device__ float g_o[(size_t)B_ * T_ * D_];

__device__ __forceinline__ float to_tf32(float x) {
    float r;
    asm("cvt.rna.tf32.f32 %0, %1;" : "=f"(r) : "f"(x));
    return r;
}

__device__ __forceinline__ uint32_t cvt_u(uint32_t x) {
    return __float_as_uint(to_tf32(__uint_as_float(x)));
}

__device__ __forceinline__ void mma_tf32(float* d, const uint32_t* a, const uint32_t* b) {
    asm volatile(
        "mma.sync.aligned.m16n8k8.row.col.f32.tf32.tf32.f32 "
        "{%0,%1,%2,%3}, {%4,%5,%6,%7}, {%8,%9}, {%0,%1,%2,%3};"
        : "+f"(d[0]), "+f"(d[1]), "+f"(d[2]), "+f"(d[3])
        : "r"(a[0]), "r"(a[1]), "r"(a[2]), "r"(a[3]), "r"(b[0]), "r"(b[1]));
}

__device__ __forceinline__ uint32_t smem_u32(const void* p) {
    return (uint32_t)__cvta_generic_to_shared(p);
}

__device__ __forceinline__ void ldm_x4(uint32_t* r, uint32_t a) {
    asm volatile("ldmatrix.sync.aligned.m8n8.x4.shared.b16 {%0,%1,%2,%3}, [%4];"
        : "=r"(r[0]), "=r"(r[1]), "=r"(r[2]), "=r"(r[3]) : "r"(a));
}

__device__ __forceinline__ void cp16(uint32_t dst, const void* src) {
    asm volatile("cp.async.cg.shared.global [%0], [%1], 16;" :: "r"(dst), "l"(src));
}
__device__ __forceinline__ void cp_commit() {
    asm volatile("cp.async.commit_group;");
}
__device__ __forceinline__ void cp_wait2() {
    asm volatile("cp.async.wait_group 2;");
}

// ---------------------------------------------------------------------------
// TF32 GEMM NT core (128x128 tile, K-chunk 16, 8 warps 2m x 4n)
// 3-stage cp.async pipeline, ldmatrix + post-load tf32 cvt, 2 CTAs/SM.
// ---------------------------------------------------------------------------
#define GP 20
#define SBYTES (128 * GP * 4)

#define GEMM_BODY(BSEL, NBASE)                                                             \
    __shared__ float As[3][128][GP];                                                       \
    __shared__ float Bs[3][128][GP];                                                       \
    const int m0   = blockIdx.y * 128;                                                     \
    const int t    = threadIdx.x;                                                          \
    const int lane = t & 31;                                                               \
    const int wid  = t >> 5;                                                               \
    const int wm   = (wid >> 2) * 64;                                                      \
    const int wn   = (wid & 3) * 32;                                                       \
    const int lr = t >> 1;                                                                 \
    const int kg = (t & 1) * 8;                                                            \
    const uint32_t As_u = smem_u32(&As[0][0][0]);                                          \
    const uint32_t Bs_u = smem_u32(&Bs[0][0][0]);                                          \
    const uint32_t a_st = As_u + 4u * (lr * GP + kg);                                      \
    const uint32_t b_st = Bs_u + 4u * (lr * GP + kg);                                      \
    const int a_off = ((lane & 7) + ((lane >> 3) & 1) * 8) * GP + ((lane >> 4) & 1) * 4;   \
    const int b_off = ((lane & 7) + ((lane >> 4) & 1) * 8) * GP + ((lane >> 3) & 1) * 4;   \
    float acc[4][4][4];                                                                    \
    _Pragma("unroll") for (int i = 0; i < 4; i++)                                          \
    _Pragma("unroll") for (int j = 0; j < 4; j++)                                          \
    _Pragma("unroll") for (int r = 0; r < 4; r++) acc[i][j][r] = 0.f;                      \
    const float* Abase = A + (size_t)(m0 + lr) * K + kg;                                   \
    const float* Bbase = (BSEL) + (size_t)((NBASE) + lr) * K + kg;                         \
    const int nk = K / 16;                                                                 \
    _Pragma("unroll") for (int s = 0; s < 2; s++) {                                        \
        cp16(a_st + s * SBYTES,      Abase + s * 16);                                      \
        cp16(a_st + s * SBYTES + 16, Abase + s * 16 + 4);                                  \
        cp16(b_st + s * SBYTES,      Bbase + s * 16);                                      \
        cp16(b_st + s * SBYTES + 16, Bbase + s * 16 + 4);                                  \
        cp_commit();                                                                       \
    }                                                                                      \
    for (int it = 0; it < nk; it++) {                                                      \
        if (it + 2 < nk) {                                                                 \
            const int buf = (it + 2) % 3;                                                  \
            cp16(a_st + buf * SBYTES,      Abase + (it + 2) * 16);                         \
            cp16(a_st + buf * SBYTES + 16, Abase + (it + 2) * 16 + 4);                     \
            cp16(b_st + buf * SBYTES,      Bbase + (it + 2) * 16);                         \
            cp16(b_st + buf * SBYTES + 16, Bbase + (it + 2) * 16 + 4);                     \
        }                                                                                  \
        cp_commit();                                                                       \
        cp_wait2();                                                                        \
        __syncthreads();                                                                   \
        const int cur = it % 3;                                                            \
        const uint32_t abuf = As_u + (uint32_t)cur * SBYTES;                               \
        const uint32_t bbuf = Bs_u + (uint32_t)cur * SBYTES;                               \
        _Pragma("unroll")                                                                  \
        for (int ks = 0; ks < 16; ks += 8) {                                               \
            uint32_t af[4][4], bf[2][4];                                                   \
            _Pragma("unroll") for (int mf = 0; mf < 4; mf++) {                             \
                ldm_x4(af[mf], abuf + 4u * ((wm + mf * 16) * GP + ks + a_off));            \
                _Pragma("unroll") for (int r = 0; r < 4; r++) af[mf][r] = cvt_u(af[mf][r]);\
            }                                                                              \
            _Pragma("unroll") for (int np = 0; np < 2; np++) {                             \
                ldm_x4(bf[np], bbuf + 4u * ((wn + np * 16) * GP + ks + b_off));            \
                _Pragma("unroll") for (int r = 0; r < 4; r++) bf[np][r] = cvt_u(bf[np][r]);\
            }                                                                              \
            _Pragma("unroll") for (int mf = 0; mf < 4; mf++)                               \
            _Pragma("unroll") for (int np = 0; np < 2; np++) {                             \
                mma_tf32(acc[mf][np * 2],     af[mf], bf[np]);                             \
                mma_tf32(acc[mf][np * 2 + 1], af[mf], bf[np] + 2);                         \
            }                                                                              \
        }                                                                                  \
        __syncthreads();                                                                   \
    }                                                                                      \
    const int n0 = blockIdx.x * 128;                                                       \
    _Pragma("unroll") for (int mf = 0; mf < 4; mf++)                                       \
    _Pragma("unroll") for (int nf = 0; nf < 4; nf++) {                                     \
        const int row = m0 + wm + mf * 16 + (lane >> 2);                                   \
        const int col = n0 + wn + nf * 8 + (lane & 3) * 2;                                 \
        *(float2*)(C + (size_t)row * N + col)       = make_float2(acc[mf][nf][0], acc[mf][nf][1]); \
        *(float2*)(C + (size_t)(row + 8) * N + col) = make_float2(acc[mf][nf][2], acc[mf][nf][3]); \
    }

__global__ __launch_bounds__(256, 2) void gemm_tf32_nt(
    const float* __restrict__ A, const float* __restrict__ B,
    float* __restrict__ C, int M, int N, int K)
{
    GEMM_BODY(B, blockIdx.x * 128)
}

__global__ __launch_bounds__(256, 2) void gemm_qkv(
    const float* __restrict__ A, const float* __restrict__ Wq,
    const float* __restrict__ Wk, const float* __restrict__ Wv,
    float* __restrict__ C, int M, int K)
{
    const int N = QKVD;
    const int nblk = blockIdx.x * 128;
    const float* Bsel; int nbase;
    if (nblk < KOFF)      { Bsel = Wq; nbase = nblk; }
    else if (nblk < VOFF) { Bsel = Wk; nbase = nblk - KOFF; }
    else                  { Bsel = Wv; nbase = nblk - VOFF; }
    GEMM_BODY(Bsel, nbase)
}

// ---------------------------------------------------------------------------
// RoPE in-place on g_qkv; q scaled by q_gain[h] * 1/sqrt(HD).
// ---------------------------------------------------------------------------
__global__ void rope_kernel(const float* __restrict__ q_gain)
{
    const int total_q = B_ * T_ * H_ * (HD_ / 2);
    const int total_k = B_ * T_ * HKV_ * (HD_ / 2);
    int idx = blockIdx.x * blockDim.x + threadIdx.x;
    if (idx >= total_q + total_k) return;

    const float LN = logf(10000.0f);
    if (idx < total_q) {
        int j = idx & 31;
        int h = (idx >> 5) & 15;
        int t = (idx >> 9) & 2047;
        int b = idx >> 20;
        float invf = expf(-LN * ((float)(2 * j) / (float)HD_));
        float f = (float)t * invf;
        float c = cosf(f), s = sinf(f);
        float* base = g_qkv + ((size_t)(b * T_ + t)) * QKVD + h * HD_;
        float x1 = base[j], x2 = base[j + 32];
        float gain = q_gain[h] * 0.125f;
        base[j]      = (x1 * c - x2 * s) * gain;
        base[j + 32] = (x1 * s + x2 * c) * gain;
    } else {
        int i2 = idx - total_q;
        int j  = i2 & 31;
        int kv = (i2 >> 5) & 3;
        int t  = (i2 >> 7) & 2047;
        int b  = i2 >> 18;
        float invf = expf(-LN * ((float)(2 * j) / (float)HD_));
        float f = (float)t * invf;
        float c = cosf(f), s = sinf(f);
        float* base = g_qkv + ((size_t)(b * T_ + t)) * QKVD + KOFF + kv * HD_;
        float x1 = base[j], x2 = base[j + 32];
        base[j]      = x1 * c - x2 * s;
        base[j + 32] = x1 * s + x2 * c;
    }
}

// ---------------------------------------------------------------------------
// Tensor-core flash attention (causal, GQA), ldmatrix fragment loads.
// Block: 256 thr (8 warps), BM=128 q rows (16/warp), BN=64 kv, HD=64.
// K stored [s][d]; V stored TRANSPOSED [d][s] with 16B-group swizzle;
// P stored [q][s]. Pitch 76 -> conflict-free ldmatrix phases. 2 CTAs/SM.
// ---------------------------------------------------------------------------
#define FP 76
#define FLASH_SMEM (256 * FP * 4)   // Ks 64 rows + Vt 64 rows + Ps 128 rows

__global__ __launch_bounds__(256, 2) void flash_tc()
{
    extern __shared__ float sm[];
    float* Ks = sm;                 // [64 s][FP]  (cols = d)
    float* Vt = sm + 64 * FP;       // [64 d][FP]  (cols = s, swizzled 16B groups)
    float* Ps = sm + 128 * FP;      // [128 q][FP] (cols = s)

    const int qt   = (int)gridDim.x - 1 - (int)blockIdx.x;  // heavy blocks first
    const int h    = blockIdx.y;
    const int b    = blockIdx.z;
    const int tid  = threadIdx.x;
    const int lane = tid & 31;
    const int wid  = tid >> 5;
    const int wm   = wid * 16;
    const int kvh  = h >> 2;
    const int r0   = lane >> 2;
    const int c0   = lane & 3;

    const uint32_t Ks_u = smem_u32(Ks);
    const uint32_t Vt_u = smem_u32(Vt);
    const uint32_t Ps_u = smem_u32(Ps);

    // ldmatrix per-lane offsets (in floats)
    const int kf_off = (lane & 7) * FP + (lane >> 3) * 4;                       // K/V frag
    const int pa_off = ((lane & 7) + ((lane >> 3) & 1) * 8) * FP + ((lane >> 4) & 1) * 4; // P frag
    const int v_row  = lane & 7;
    const int v_cb   = lane >> 3;

    // Q fragments in registers (tf32)
    uint32_t qf[8][4];
    {
        const float* q0 = g_qkv + ((size_t)(b * T_ + qt * 128 + wm + r0)) * QKVD + h * HD_;
        const float* q1 = q0 + (size_t)8 * QKVD;
#pragma unroll
        for (int kb = 0; kb < 8; kb++) {
            qf[kb][0] = __float_as_uint(to_tf32(q0[kb * 8 + c0]));
            qf[kb][1] = __float_as_uint(to_tf32(q1[kb * 8 + c0]));
            qf[kb][2] = __float_as_uint(to_tf32(q0[kb * 8 + c0 + 4]));
            qf[kb][3] = __float_as_uint(to_tf32(q1[kb * 8 + c0 + 4]));
        }
    }

    float oacc[8][4];
#pragma unroll
    for (int nf = 0; nf < 8; nf++)
#pragma unroll
        for (int r = 0; r < 4; r++) oacc[nf][r] = 0.f;
    float m0v = -1e30f, m1v = -1e30f, l0 = 0.f, l1 = 0.f;

    const int qi0 = qt * 128 + wm + r0;
    const int qi1 = qi0 + 8;
    const int s_end = (qt + 1) * 128;

    for (int s0 = 0; s0 < s_end; s0 += 64) {
        // cooperative K load (row-major) + V transpose-store (swizzled)
        {
            const int row = tid >> 2;            // kv position 0..63
            const int cg  = (tid & 3) * 16;      // d group
            const int swz = tid & 3;             // = (d>>4)&3 for this thread's d range
            const float* ksrc = g_qkv + ((size_t)(b * T_ + s0 + row)) * QKVD + KOFF + kvh * HD_ + cg;
            const float* vsrc = ksrc + (VOFF - KOFF);
#pragma unroll
            for (int u = 0; u < 4; u++) {
                float4 k4 = *(const float4*)(ksrc + u * 4);
                float4 v4 = *(const float4*)(vsrc + u * 4);
                *(float4*)&Ks[row * FP + cg + u * 4] =
                    make_float4(to_tf32(k4.x), to_tf32(k4.y), to_tf32(k4.z), to_tf32(k4.w));
                const int pg = ((row >> 2) ^ swz) * 4 + (row & 3);
                float vv[4] = {v4.x, v4.y, v4.z, v4.w};
#pragma unroll
                for (int e = 0; e < 4; e++)
                    Vt[(cg + u * 4 + e) * FP + pg] = to_tf32(vv[e]);
            }
        }
        __syncthreads();

        if (s0 <= qt * 128 + wm + 15) {   // warp has at least one unmasked row
            // S = Q @ K^T   (per-warp 16x64)
            float sacc[8][4];
#pragma unroll
            for (int nf = 0; nf < 8; nf++)
#pragma unroll
                for (int r = 0; r < 4; r++) sacc[nf][r] = 0.f;

#pragma unroll
            for (int kbp = 0; kbp < 4; kbp++) {
#pragma unroll
                for (int nf = 0; nf < 8; nf++) {
                    uint32_t kb4[4];
                    ldm_x4(kb4, Ks_u + 4u * (nf * 8 * FP + kbp * 16 + kf_off));
                    mma_tf32(sacc[nf], qf[2 * kbp],     kb4);
                    mma_tf32(sacc[nf], qf[2 * kbp + 1], kb4 + 2);
                }
            }

            // causal mask (only near the diagonal)
            if (s0 + 63 > qt * 128 + wm) {
#pragma unroll
                for (int nf = 0; nf < 8; nf++) {
                    int sj = s0 + nf * 8 + 2 * c0;
                    if (sj > qi0)     sacc[nf][0] = -1e30f;
                    if (sj + 1 > qi0) sacc[nf][1] = -1e30f;
                    if (sj > qi1)     sacc[nf][2] = -1e30f;
                    if (sj + 1 > qi1) sacc[nf][3] = -1e30f;
                }
            }

            // row maxes
            float tm0 = -1e30f, tm1 = -1e30f;
#pragma unroll
            for (int nf = 0; nf < 8; nf++) {
                tm0 = fmaxf(tm0, fmaxf(sacc[nf][0], sacc[nf][1]));
                tm1 = fmaxf(tm1, fmaxf(sacc[nf][2], sacc[nf][3]));
            }
            tm0 = fmaxf(tm0, __shfl_xor_sync(0xffffffff, tm0, 1));
            tm0 = fmaxf(tm0, __shfl_xor_sync(0xffffffff, tm0, 2));
            tm1 = fmaxf(tm1, __shfl_xor_sync(0xffffffff, tm1, 1));
            tm1 = fmaxf(tm1, __shfl_xor_sync(0xffffffff, tm1, 2));

            float mn0 = fmaxf(m0v, tm0), mn1 = fmaxf(m1v, tm1);
            float cor0 = __expf(m0v - mn0), cor1 = __expf(m1v - mn1);

            // exp, tf32-round, store P, partial sums (sum the ROUNDED values)
            float ps0 = 0.f, ps1 = 0.f;
#pragma unroll
            for (int nf = 0; nf < 8; nf++) {
                float p0 = to_tf32(__expf(sacc[nf][0] - mn0));
                float p1 = to_tf32(__expf(sacc[nf][1] - mn0));
                float p2 = to_tf32(__expf(sacc[nf][2] - mn1));
                float p3 = to_tf32(__expf(sacc[nf][3] - mn1));
                ps0 += p0 + p1; ps1 += p2 + p3;
                *(float2*)&Ps[(wm + r0)     * FP + nf * 8 + 2 * c0] = make_float2(p0, p1);
                *(float2*)&Ps[(wm + r0 + 8) * FP + nf * 8 + 2 * c0] = make_float2(p2, p3);
            }
            ps0 += __shfl_xor_sync(0xffffffff, ps0, 1);
            ps0 += __shfl_xor_sync(0xffffffff, ps0, 2);
            ps1 += __shfl_xor_sync(0xffffffff, ps1, 1);
            ps1 += __shfl_xor_sync(0xffffffff, ps1, 2);
            l0 = l0 * cor0 + ps0;
            l1 = l1 * cor1 + ps1;

#pragma unroll
            for (int nf = 0; nf < 8; nf++) {
                oacc[nf][0] *= cor0; oacc[nf][1] *= cor0;
                oacc[nf][2] *= cor1; oacc[nf][3] *= cor1;
            }
            m0v = mn0; m1v = mn1;

            __syncwarp();

            // O += P @ V   (per-warp 16x64, K=64) — P and V via ldmatrix
#pragma unroll
            for (int kbp = 0; kbp < 4; kbp++) {
                uint32_t pa0[4], pa1[4];
                ldm_x4(pa0, Ps_u + 4u * (wm * FP + (2 * kbp)     * 8 + pa_off));
                ldm_x4(pa1, Ps_u + 4u * (wm * FP + (2 * kbp + 1) * 8 + pa_off));
#pragma unroll
                for (int nf = 0; nf < 8; nf++) {
                    uint32_t vb[4];
                    const int pg = (kbp * 4 + v_cb) ^ ((nf >> 1) & 3);
                    ldm_x4(vb, Vt_u + 4u * ((nf * 8 + v_row) * FP + pg * 4));
                    mma_tf32(oacc[nf], pa0, vb);
                    mma_tf32(oacc[nf], pa1, vb + 2);
                }
            }
        }
        __syncthreads();
    }

    // epilogue: normalize, write O
    float il0 = 1.0f / l0, il1 = 1.0f / l1;
    float* o0 = g_o + ((size_t)(b * T_ + qi0)) * D_ + h * HD_;
    float* o1 = g_o + ((size_t)(b * T_ + qi1)) * D_ + h * HD_;
#pragma unroll
    for (int nf = 0; nf < 8; nf++) {
        *(float2*)(o0 + nf * 8 + 2 * c0) = make_float2(oacc[nf][0] * il0, oacc[nf][1] * il0);
        *(float2*)(o1 + nf * 8 + 2 * c0) = make_float2(oacc[nf][2] * il1, oacc[nf][3] * il1);
    }
}

// ---------------------------------------------------------------------------
// Launch
// ---------------------------------------------------------------------------
extern "C" void kernel_launch(void* const* d_in, const int* in_sizes, int n_in,
                              void* d_out, int out_size)
{
    (void)in_sizes; (void)n_in; (void)out_size;
    const float* x      = (const float*)d_in[0];
    const float* Wq     = (const float*)d_in[1];
    const float* Wk     = (const float*)d_in[2];
    const float* Wv     = (const float*)d_in[3];
    const float* Wp     = (const float*)d_in[4];
    const float* q_gain = (const float*)d_in[5];
    float* out = (float*)d_out;

    float *qkvb, *ob;
    cudaGetSymbolAddress((void**)&qkvb, g_qkv);
    cudaGetSymbolAddress((void**)&ob, g_o);

    cudaFuncSetAttribute(flash_tc, cudaFuncAttributeMaxDynamicSharedMemorySize, FLASH_SMEM);

    const int M = B_ * T_;   // 4096

    // Fused QKV projection
    gemm_qkv<<<dim3(QKVD / 128, M / 128), 256>>>(x, Wq, Wk, Wv, qkvb, M, D_);

    // RoPE + gain/scale (in place)
    const int total = B_ * T_ * (H_ + HKV_) * (HD_ / 2);
    rope_kernel<<<(total + 255) / 256, 256>>>(q_gain);

    // Tensor-core causal flash attention
    flash_tc<<<dim3(T_ / 128, H_, B_), 256, FLASH_SMEM>>>();

    // Output projection
    gemm_tf32_nt<<<dim3(D_ / 128, M / 128), 256>>>(ob, Wp, out, M, D_, D_);
}

// round 6
// speedup vs baseline: 4.0235x; 1.0272x over previous
#include <cuda_runtime.h>
#include <math.h>
#include <stdint.h>

#define B_   2
#define T_   2048
#define D_   1024
#define H_   16
#define HKV_ 4
#define HD_  64
#define G_   4

#define QKVD 1536      // fused qkv row width: 1024 q | 256 k | 256 v
#define KOFF 1024
#define VOFF 1280

// Scratch (static device globals — no allocation in kernel_launch)
__device__ float g_qkv[(size_t)B_ * T_ * QKVD];
__device__ float g_o[(size_t)B_ * T_ * D_];
// pre-rounded (tf32) copies: x | Wq | Wk | Wv | Wp
#define PRE_X  0
#define PRE_WQ (4096 * 1024)
#define PRE_WK (PRE_WQ + 1024 * 1024)
#define PRE_WV (PRE_WK + 256 * 1024)
#define PRE_WP (PRE_WV + 256 * 1024)
#define PRE_TOTAL (PRE_WP + 1024 * 1024)
__device__ float g_pre[(size_t)PRE_TOTAL];

__device__ __forceinline__ float to_tf32(float x) {
    float r;
    asm("cvt.rna.tf32.f32 %0, %1;" : "=f"(r) : "f"(x));
    return r;
}

__device__ __forceinline__ void mma_tf32(float* d, const uint32_t* a, const uint32_t* b) {
    asm volatile(
        "mma.sync.aligned.m16n8k8.row.col.f32.tf32.tf32.f32 "
        "{%0,%1,%2,%3}, {%4,%5,%6,%7}, {%8,%9}, {%0,%1,%2,%3};"
        : "+f"(d[0]), "+f"(d[1]), "+f"(d[2]), "+f"(d[3])
        : "r"(a[0]), "r"(a[1]), "r"(a[2]), "r"(a[3]), "r"(b[0]), "r"(b[1]));
}

__device__ __forceinline__ uint32_t smem_u32(const void* p) {
    return (uint32_t)__cvta_generic_to_shared(p);
}

__device__ __forceinline__ void ldm_x4(uint32_t* r, uint32_t a) {
    asm volatile("ldmatrix.sync.aligned.m8n8.x4.shared.b16 {%0,%1,%2,%3}, [%4];"
        : "=r"(r[0]), "=r"(r[1]), "=r"(r[2]), "=r"(r[3]) : "r"(a));
}

__device__ __forceinline__ void cp16(uint32_t dst, const void* src) {
    asm volatile("cp.async.cg.shared.global [%0], [%1], 16;" :: "r"(dst), "l"(src));
}
__device__ __forceinline__ void cp_commit() {
    asm volatile("cp.async.commit_group;");
}
__device__ __forceinline__ void cp_wait1() {
    asm volatile("cp.async.wait_group 1;");
}

// ---------------------------------------------------------------------------
// Pre-round inputs to tf32 (rna) into g_pre. float4 vectorized.
// ---------------------------------------------------------------------------
__global__ void preround_kernel(const float* __restrict__ x,
                                const float* __restrict__ Wq,
                                const float* __restrict__ Wk,
                                const float* __restrict__ Wv,
                                const float* __restrict__ Wp)
{
    int i4 = blockIdx.x * blockDim.x + threadIdx.x;   // float4 index
    int i = i4 * 4;
    if (i >= PRE_TOTAL) return;
    const float* src;
    int off;
    if (i < PRE_WQ)      { src = x;  off = i - PRE_X;  }
    else if (i < PRE_WK) { src = Wq; off = i - PRE_WQ; }
    else if (i < PRE_WV) { src = Wk; off = i - PRE_WK; }
    else if (i < PRE_WP) { src = Wv; off = i - PRE_WV; }
    else                 { src = Wp; off = i - PRE_WP; }
    float4 v = *(const float4*)(src + off);
    *(float4*)(g_pre + i) = make_float4(to_tf32(v.x), to_tf32(v.y), to_tf32(v.z), to_tf32(v.w));
}

// ---------------------------------------------------------------------------
// TF32 GEMM NT core (128x128 tile, K-chunk 16, 8 warps 2m x 4n)
// 3-stage cp.async, single barrier per chunk, NO inner-loop cvt.
// Inputs must already be tf32-rounded. ROUND controls epilogue rounding.
// ---------------------------------------------------------------------------
#define GP 20
#define SBYTES (128 * GP * 4)

#define GEMM_BODY(BSEL, NBASE, ROUND)                                                      \
    __shared__ float As[3][128][GP];                                                       \
    __shared__ float Bs[3][128][GP];                                                       \
    const int m0   = blockIdx.y * 128;                                                     \
    const int t    = threadIdx.x;                                                          \
    const int lane = t & 31;                                                               \
    const int wid  = t >> 5;                                                               \
    const int wm   = (wid >> 2) * 64;                                                      \
    const int wn   = (wid & 3) * 32;                                                       \
    const int lr = t >> 1;                                                                 \
    const int kg = (t & 1) * 8;                                                            \
    const uint32_t As_u = smem_u32(&As[0][0][0]);                                          \
    const uint32_t Bs_u = smem_u32(&Bs[0][0][0]);                                          \
    const uint32_t a_st = As_u + 4u * (lr * GP + kg);                                      \
    const uint32_t b_st = Bs_u + 4u * (lr * GP + kg);                                      \
    const int a_off = ((lane & 7) + ((lane >> 3) & 1) * 8) * GP + ((lane >> 4) & 1) * 4;   \
    const int b_off = ((lane & 7) + ((lane >> 4) & 1) * 8) * GP + ((lane >> 3) & 1) * 4;   \
    float acc[4][4][4];                                                                    \
    _Pragma("unroll") for (int i = 0; i < 4; i++)                                          \
    _Pragma("unroll") for (int j = 0; j < 4; j++)                                          \
    _Pragma("unroll") for (int r = 0; r < 4; r++) acc[i][j][r] = 0.f;                      \
    const float* Abase = A + (size_t)(m0 + lr) * K + kg;                                   \
    const float* Bbase = (BSEL) + (size_t)((NBASE) + lr) * K + kg;                         \
    const int nk = K / 16;                                                                 \
    _Pragma("unroll") for (int s = 0; s < 2; s++) {                                        \
        cp16(a_st + s * SBYTES,      Abase + s * 16);                                      \
        cp16(a_st + s * SBYTES + 16, Abase + s * 16 + 4);                                  \
        cp16(b_st + s * SBYTES,      Bbase + s * 16);                                      \
        cp16(b_st + s * SBYTES + 16, Bbase + s * 16 + 4);                                  \
        cp_commit();                                                                       \
    }                                                                                      \
    for (int it = 0; it < nk; it++) {                                                      \
        cp_wait1();                                                                        \
        __syncthreads();                                                                   \
        if (it + 2 < nk) {                                                                 \
            const int buf = (it + 2) % 3;                                                  \
            cp16(a_st + buf * SBYTES,      Abase + (it + 2) * 16);                         \
            cp16(a_st + buf * SBYTES + 16, Abase + (it + 2) * 16 + 4);                     \
            cp16(b_st + buf * SBYTES,      Bbase + (it + 2) * 16);                         \
            cp16(b_st + buf * SBYTES + 16, Bbase + (it + 2) * 16 + 4);                     \
        }                                                                                  \
        cp_commit();                                                                       \
        const int cur = it % 3;                                                            \
        const uint32_t abuf = As_u + (uint32_t)cur * SBYTES;                               \
        const uint32_t bbuf = Bs_u + (uint32_t)cur * SBYTES;                               \
        uint32_t af[2][4][4], bf[2][2][4];                                                 \
        _Pragma("unroll") for (int ks2 = 0; ks2 < 2; ks2++) {                              \
            _Pragma("unroll") for (int mf = 0; mf < 4; mf++)                               \
                ldm_x4(af[ks2][mf], abuf + 4u * ((wm + mf * 16) * GP + ks2 * 8 + a_off));  \
            _Pragma("unroll") for (int np = 0; np < 2; np++)                               \
                ldm_x4(bf[ks2][np], bbuf + 4u * ((wn + np * 16) * GP + ks2 * 8 + b_off));  \
        }                                                                                  \
        _Pragma("unroll") for (int ks2 = 0; ks2 < 2; ks2++)                                \
        _Pragma("unroll") for (int mf = 0; mf < 4; mf++)                                   \
        _Pragma("unroll") for (int np = 0; np < 2; np++) {                                 \
            mma_tf32(acc[mf][np * 2],     af[ks2][mf], bf[ks2][np]);                       \
            mma_tf32(acc[mf][np * 2 + 1], af[ks2][mf], bf[ks2][np] + 2);                   \
        }                                                                                  \
    }                                                                                      \
    const int n0 = blockIdx.x * 128;                                                       \
    _Pragma("unroll") for (int mf = 0; mf < 4; mf++)                                       \
    _Pragma("unroll") for (int nf = 0; nf < 4; nf++) {                                     \
        const int row = m0 + wm + mf * 16 + (lane >> 2);                                   \
        const int col = n0 + wn + nf * 8 + (lane & 3) * 2;                                 \
        *(float2*)(C + (size_t)row * N + col)       = make_float2(ROUND(acc[mf][nf][0]), ROUND(acc[mf][nf][1])); \
        *(float2*)(C + (size_t)(row + 8) * N + col) = make_float2(ROUND(acc[mf][nf][2]), ROUND(acc[mf][nf][3])); \
    }

#define NOROUND(v) (v)

__global__ __launch_bounds__(256, 2) void gemm_tf32_nt(
    const float* __restrict__ A, const float* __restrict__ B,
    float* __restrict__ C, int M, int N, int K)
{
    GEMM_BODY(B, blockIdx.x * 128, NOROUND)
}

__global__ __launch_bounds__(256, 2) void gemm_qkv(
    const float* __restrict__ A, const float* __restrict__ Wq,
    const float* __restrict__ Wk, const float* __restrict__ Wv,
    float* __restrict__ C, int M, int K)
{
    const int N = QKVD;
    const int nblk = blockIdx.x * 128;
    const float* Bsel; int nbase;
    if (nblk < KOFF)      { Bsel = Wq; nbase = nblk; }
    else if (nblk < VOFF) { Bsel = Wk; nbase = nblk - KOFF; }
    else                  { Bsel = Wv; nbase = nblk - VOFF; }
    GEMM_BODY(Bsel, nbase, to_tf32)   // qkv outputs feed tf32 mma consumers
}

// ---------------------------------------------------------------------------
// RoPE in-place on g_qkv; q scaled by q_gain[h] * 1/sqrt(HD). tf32 outputs.
// ---------------------------------------------------------------------------
__global__ void rope_kernel(const float* __restrict__ q_gain)
{
    const int total_q = B_ * T_ * H_ * (HD_ / 2);
    const int total_k = B_ * T_ * HKV_ * (HD_ / 2);
    int idx = blockIdx.x * blockDim.x + threadIdx.x;
    if (idx >= total_q + total_k) return;

    const float LN = logf(10000.0f);
    if (idx < total_q) {
        int j = idx & 31;
        int h = (idx >> 5) & 15;
        int t = (idx >> 9) & 2047;
        int b = idx >> 20;
        float invf = expf(-LN * ((float)(2 * j) / (float)HD_));
        float f = (float)t * invf;
        float c = cosf(f), s = sinf(f);
        float* base = g_qkv + ((size_t)(b * T_ + t)) * QKVD + h * HD_;
        float x1 = base[j], x2 = base[j + 32];
        float gain = q_gain[h] * 0.125f;
        base[j]      = to_tf32((x1 * c - x2 * s) * gain);
        base[j + 32] = to_tf32((x1 * s + x2 * c) * gain);
    } else {
        int i2 = idx - total_q;
        int j  = i2 & 31;
        int kv = (i2 >> 5) & 3;
        int t  = (i2 >> 7) & 2047;
        int b  = i2 >> 18;
        float invf = expf(-LN * ((float)(2 * j) / (float)HD_));
        float f = (float)t * invf;
        float c = cosf(f), s = sinf(f);
        float* base = g_qkv + ((size_t)(b * T_ + t)) * QKVD + KOFF + kv * HD_;
        float x1 = base[j], x2 = base[j + 32];
        base[j]      = to_tf32(x1 * c - x2 * s);
        base[j + 32] = to_tf32(x1 * s + x2 * c);
    }
}

// ---------------------------------------------------------------------------
// Tensor-core flash attention (causal, GQA), ldmatrix fragment loads.
// All inputs already tf32-rounded -> no cvt on K/V/Q loads.
// ---------------------------------------------------------------------------
#define FP 76
#define FLASH_SMEM (256 * FP * 4)   // Ks 64 rows + Vt 64 rows + Ps 128 rows

__global__ __launch_bounds__(256, 2) void flash_tc()
{
    extern __shared__ float sm[];
    float* Ks = sm;                 // [64 s][FP]  (cols = d)
    float* Vt = sm + 64 * FP;       // [64 d][FP]  (cols = s, swizzled 16B groups)
    float* Ps = sm + 128 * FP;      // [128 q][FP] (cols = s)

    const int qt   = (int)gridDim.x - 1 - (int)blockIdx.x;  // heavy blocks first
    const int h    = blockIdx.y;
    const int b    = blockIdx.z;
    const int tid  = threadIdx.x;
    const int lane = tid & 31;
    const int wid  = tid >> 5;
    const int wm   = wid * 16;
    const int kvh  = h >> 2;
    const int r0   = lane >> 2;
    const int c0   = lane & 3;

    const uint32_t Ks_u = smem_u32(Ks);
    const uint32_t Vt_u = smem_u32(Vt);
    const uint32_t Ps_u = smem_u32(Ps);

    const int kf_off = (lane & 7) * FP + (lane >> 3) * 4;
    const int pa_off = ((lane & 7) + ((lane >> 3) & 1) * 8) * FP + ((lane >> 4) & 1) * 4;
    const int v_row  = lane & 7;
    const int v_cb   = lane >> 3;

    // Q fragments in registers (already tf32)
    uint32_t qf[8][4];
    {
        const float* q0 = g_qkv + ((size_t)(b * T_ + qt * 128 + wm + r0)) * QKVD + h * HD_;
        const float* q1 = q0 + (size_t)8 * QKVD;
#pragma unroll
        for (int kb = 0; kb < 8; kb++) {
            qf[kb][0] = __float_as_uint(q0[kb * 8 + c0]);
            qf[kb][1] = __float_as_uint(q1[kb * 8 + c0]);
            qf[kb][2] = __float_as_uint(q0[kb * 8 + c0 + 4]);
            qf[kb][3] = __float_as_uint(q1[kb * 8 + c0 + 4]);
        }
    }

    float oacc[8][4];
#pragma unroll
    for (int nf = 0; nf < 8; nf++)
#pragma unroll
        for (int r = 0; r < 4; r++) oacc[nf][r] = 0.f;
    float m0v = -1e30f, m1v = -1e30f, l0 = 0.f, l1 = 0.f;

    const int qi0 = qt * 128 + wm + r0;
    const int qi1 = qi0 + 8;
    const int s_end = (qt + 1) * 128;

    for (int s0 = 0; s0 < s_end; s0 += 64) {
        // cooperative K load (row-major) + V transpose-store (swizzled)
        {
            const int row = tid >> 2;
            const int cg  = (tid & 3) * 16;
            const int swz = tid & 3;
            const float* ksrc = g_qkv + ((size_t)(b * T_ + s0 + row)) * QKVD + KOFF + kvh * HD_ + cg;
            const float* vsrc = ksrc + (VOFF - KOFF);
#pragma unroll
            for (int u = 0; u < 4; u++) {
                float4 k4 = *(const float4*)(ksrc + u * 4);
                float4 v4 = *(const float4*)(vsrc + u * 4);
                *(float4*)&Ks[row * FP + cg + u * 4] = k4;
                const int pg = ((row >> 2) ^ swz) * 4 + (row & 3);
                Vt[(cg + u * 4 + 0) * FP + pg] = v4.x;
                Vt[(cg + u * 4 + 1) * FP + pg] = v4.y;
                Vt[(cg + u * 4 + 2) * FP + pg] = v4.z;
                Vt[(cg + u * 4 + 3) * FP + pg] = v4.w;
            }
        }
        __syncthreads();

        if (s0 <= qt * 128 + wm + 15) {
            // S = Q @ K^T   (per-warp 16x64)
            float sacc[8][4];
#pragma unroll
            for (int nf = 0; nf < 8; nf++)
#pragma unroll
                for (int r = 0; r < 4; r++) sacc[nf][r] = 0.f;

#pragma unroll
            for (int kbp = 0; kbp < 4; kbp++) {
#pragma unroll
                for (int nf = 0; nf < 8; nf++) {
                    uint32_t kb4[4];
                    ldm_x4(kb4, Ks_u + 4u * (nf * 8 * FP + kbp * 16 + kf_off));
                    mma_tf32(sacc[nf], qf[2 * kbp],     kb4);
                    mma_tf32(sacc[nf], qf[2 * kbp + 1], kb4 + 2);
                }
            }

            if (s0 + 63 > qt * 128 + wm) {
#pragma unroll
                for (int nf = 0; nf < 8; nf++) {
                    int sj = s0 + nf * 8 + 2 * c0;
                    if (sj > qi0)     sacc[nf][0] = -1e30f;
                    if (sj + 1 > qi0) sacc[nf][1] = -1e30f;
                    if (sj > qi1)     sacc[nf][2] = -1e30f;
                    if (sj + 1 > qi1) sacc[nf][3] = -1e30f;
                }
            }

            float tm0 = -1e30f, tm1 = -1e30f;
#pragma unroll
            for (int nf = 0; nf < 8; nf++) {
                tm0 = fmaxf(tm0, fmaxf(sacc[nf][0], sacc[nf][1]));
                tm1 = fmaxf(tm1, fmaxf(sacc[nf][2], sacc[nf][3]));
            }
            tm0 = fmaxf(tm0, __shfl_xor_sync(0xffffffff, tm0, 1));
            tm0 = fmaxf(tm0, __shfl_xor_sync(0xffffffff, tm0, 2));
            tm1 = fmaxf(tm1, __shfl_xor_sync(0xffffffff, tm1, 1));
            tm1 = fmaxf(tm1, __shfl_xor_sync(0xffffffff, tm1, 2));

            float mn0 = fmaxf(m0v, tm0), mn1 = fmaxf(m1v, tm1);
            float cor0 = __expf(m0v - mn0), cor1 = __expf(m1v - mn1);

            float ps0 = 0.f, ps1 = 0.f;
#pragma unroll
            for (int nf = 0; nf < 8; nf++) {
                float p0 = to_tf32(__expf(sacc[nf][0] - mn0));
                float p1 = to_tf32(__expf(sacc[nf][1] - mn0));
                float p2 = to_tf32(__expf(sacc[nf][2] - mn1));
                float p3 = to_tf32(__expf(sacc[nf][3] - mn1));
                ps0 += p0 + p1; ps1 += p2 + p3;
                *(float2*)&Ps[(wm + r0)     * FP + nf * 8 + 2 * c0] = make_float2(p0, p1);
                *(float2*)&Ps[(wm + r0 + 8) * FP + nf * 8 + 2 * c0] = make_float2(p2, p3);
            }
            ps0 += __shfl_xor_sync(0xffffffff, ps0, 1);
            ps0 += __shfl_xor_sync(0xffffffff, ps0, 2);
            ps1 += __shfl_xor_sync(0xffffffff, ps1, 1);
            ps1 += __shfl_xor_sync(0xffffffff, ps1, 2);
            l0 = l0 * cor0 + ps0;
            l1 = l1 * cor1 + ps1;

#pragma unroll
            for (int nf = 0; nf < 8; nf++) {
                oacc[nf][0] *= cor0; oacc[nf][1] *= cor0;
                oacc[nf][2] *= cor1; oacc[nf][3] *= cor1;
            }
            m0v = mn0; m1v = mn1;

            __syncwarp();

            // O += P @ V
#pragma unroll
            for (int kbp = 0; kbp < 4; kbp++) {
                uint32_t pa0[4], pa1[4];
                ldm_x4(pa0, Ps_u + 4u * (wm * FP + (2 * kbp)     * 8 + pa_off));
                ldm_x4(pa1, Ps_u + 4u * (wm * FP + (2 * kbp + 1) * 8 + pa_off));
#pragma unroll
                for (int nf = 0; nf < 8; nf++) {
                    uint32_t vb[4];
                    const int pg = (kbp * 4 + v_cb) ^ ((nf >> 1) & 3);
                    ldm_x4(vb, Vt_u + 4u * ((nf * 8 + v_row) * FP + pg * 4));
                    mma_tf32(oacc[nf], pa0, vb);
                    mma_tf32(oacc[nf], pa1, vb + 2);
                }
            }
        }
        __syncthreads();
    }

    // epilogue: normalize, tf32-round (proj GEMM consumes this), write O
    float il0 = 1.0f / l0, il1 = 1.0f / l1;
    float* o0 = g_o + ((size_t)(b * T_ + qi0)) * D_ + h * HD_;
    float* o1 = g_o + ((size_t)(b * T_ + qi1)) * D_ + h * HD_;
#pragma unroll
    for (int nf = 0; nf < 8; nf++) {
        *(float2*)(o0 + nf * 8 + 2 * c0) = make_float2(to_tf32(oacc[nf][0] * il0), to_tf32(oacc[nf][1] * il0));
        *(float2*)(o1 + nf * 8 + 2 * c0) = make_float2(to_tf32(oacc[nf][2] * il1), to_tf32(oacc[nf][3] * il1));
    }
}

// ---------------------------------------------------------------------------
// Launch
// ---------------------------------------------------------------------------
extern "C" void kernel_launch(void* const* d_in, const int* in_sizes, int n_in,
                              void* d_out, int out_size)
{
    (void)in_sizes; (void)n_in; (void)out_size;
    const float* x      = (const float*)d_in[0];
    const float* Wq     = (const float*)d_in[1];
    const float* Wk     = (const float*)d_in[2];
    const float* Wv     = (const float*)d_in[3];
    const float* Wp     = (const float*)d_in[4];
    const float* q_gain = (const float*)d_in[5];
    float* out = (float*)d_out;

    float *qkvb, *ob, *pre;
    cudaGetSymbolAddress((void**)&qkvb, g_qkv);
    cudaGetSymbolAddress((void**)&ob, g_o);
    cudaGetSymbolAddress((void**)&pre, g_pre);

    cudaFuncSetAttribute(flash_tc, cudaFuncAttributeMaxDynamicSharedMemorySize, FLASH_SMEM);

    const int M = B_ * T_;   // 4096

    // Pre-round all GEMM inputs to tf32
    preround_kernel<<<(PRE_TOTAL / 4 + 255) / 256, 256>>>(x, Wq, Wk, Wv, Wp);

    // Fused QKV projection (tf32-rounded epilogue)
    gemm_qkv<<<dim3(QKVD / 128, M / 128), 256>>>(
        pre + PRE_X, pre + PRE_WQ, pre + PRE_WK, pre + PRE_WV, qkvb, M, D_);

    // RoPE + gain/scale (in place, tf32 outputs)
    const int total = B_ * T_ * (H_ + HKV_) * (HD_ / 2);
    rope_kernel<<<(total + 255) / 256, 256>>>(q_gain);

    // Tensor-core causal flash attention
    flash_tc<<<dim3(T_ / 128, H_, B_), 256, FLASH_SMEM>>>();

    // Output projection (raw fp32 epilogue)
    gemm_tf32_nt<<<dim3(D_ / 128, M / 128), 256>>>(ob, pre + PRE_WP, out, M, D_, D_);
}

// round 7
// speedup vs baseline: 4.2533x; 1.0571x over previous
#include <cuda_runtime.h>
#include <math.h>
#include <stdint.h>

#define B_   2
#define T_   2048
#define D_   1024
#define H_   16
#define HKV_ 4
#define HD_  64
#define G_   4

#define QKVD 1536      // fused qkv row width: 1024 q | 256 k | 256 v
#define KOFF 1024
#define VOFF 1280

// Scratch (static device globals — no allocation in kernel_launch)
__device__ float g_qkv[(size_t)B_ * T_ * QKVD];
__device__ float g_vt[(size_t)B_ * HKV_ * HD_ * T_];   // V transposed: [b][kvh][d][t]
__device__ float g_o[(size_t)B_ * T_ * D_];
// pre-rounded (tf32) copies: x | Wq | Wk | Wv | Wp
#define PRE_X  0
#define PRE_WQ (4096 * 1024)
#define PRE_WK (PRE_WQ + 1024 * 1024)
#define PRE_WV (PRE_WK + 256 * 1024)
#define PRE_WP (PRE_WV + 256 * 1024)
#define PRE_TOTAL (PRE_WP + 1024 * 1024)
__device__ float g_pre[(size_t)PRE_TOTAL];

__device__ __forceinline__ float to_tf32(float x) {
    float r;
    asm("cvt.rna.tf32.f32 %0, %1;" : "=f"(r) : "f"(x));
    return r;
}

__device__ __forceinline__ void mma_tf32(float* d, const uint32_t* a, const uint32_t* b) {
    asm volatile(
        "mma.sync.aligned.m16n8k8.row.col.f32.tf32.tf32.f32 "
        "{%0,%1,%2,%3}, {%4,%5,%6,%7}, {%8,%9}, {%0,%1,%2,%3};"
        : "+f"(d[0]), "+f"(d[1]), "+f"(d[2]), "+f"(d[3])
        : "r"(a[0]), "r"(a[1]), "r"(a[2]), "r"(a[3]), "r"(b[0]), "r"(b[1]));
}

__device__ __forceinline__ uint32_t smem_u32(const void* p) {
    return (uint32_t)__cvta_generic_to_shared(p);
}

__device__ __forceinline__ void ldm_x4(uint32_t* r, uint32_t a) {
    asm volatile("ldmatrix.sync.aligned.m8n8.x4.shared.b16 {%0,%1,%2,%3}, [%4];"
        : "=r"(r[0]), "=r"(r[1]), "=r"(r[2]), "=r"(r[3]) : "r"(a));
}

__device__ __forceinline__ void cp16(uint32_t dst, const void* src) {
    asm volatile("cp.async.cg.shared.global [%0], [%1], 16;" :: "r"(dst), "l"(src));
}
__device__ __forceinline__ void cp_commit() {
    asm volatile("cp.async.commit_group;");
}
__device__ __forceinline__ void cp_wait1() {
    asm volatile("cp.async.wait_group 1;");
}

// ---------------------------------------------------------------------------
// Pre-round inputs to tf32 (rna) into g_pre.
// ---------------------------------------------------------------------------
__global__ void preround_kernel(const float* __restrict__ x,
                                const float* __restrict__ Wq,
                                const float* __restrict__ Wk,
                                const float* __restrict__ Wv,
                                const float* __restrict__ Wp)
{
    int i4 = blockIdx.x * blockDim.x + threadIdx.x;
    int i = i4 * 4;
    if (i >= PRE_TOTAL) return;
    const float* src;
    int off;
    if (i < PRE_WQ)      { src = x;  off = i - PRE_X;  }
    else if (i < PRE_WK) { src = Wq; off = i - PRE_WQ; }
    else if (i < PRE_WV) { src = Wk; off = i - PRE_WK; }
    else if (i < PRE_WP) { src = Wv; off = i - PRE_WV; }
    else                 { src = Wp; off = i - PRE_WP; }
    float4 v = *(const float4*)(src + off);
    *(float4*)(g_pre + i) = make_float4(to_tf32(v.x), to_tf32(v.y), to_tf32(v.z), to_tf32(v.w));
}

// ---------------------------------------------------------------------------
// TF32 GEMM mainloop (128x128 tile, K-chunk 16, 8 warps 2m x 4n)
// 3-stage cp.async, single barrier per chunk, no inner-loop cvt.
// ---------------------------------------------------------------------------
#define GP 20
#define SBYTES (128 * GP * 4)

#define GEMM_MAIN(BSEL, NBASE)                                                             \
    __shared__ float As[3][128][GP];                                                       \
    __shared__ float Bs[3][128][GP];                                                       \
    const int m0   = blockIdx.y * 128;                                                     \
    const int t    = threadIdx.x;                                                          \
    const int lane = t & 31;                                                               \
    const int wid  = t >> 5;                                                               \
    const int wm   = (wid >> 2) * 64;                                                      \
    const int wn   = (wid & 3) * 32;                                                       \
    const int lr = t >> 1;                                                                 \
    const int kg = (t & 1) * 8;                                                            \
    const uint32_t As_u = smem_u32(&As[0][0][0]);                                          \
    const uint32_t Bs_u = smem_u32(&Bs[0][0][0]);                                          \
    const uint32_t a_st = As_u + 4u * (lr * GP + kg);                                      \
    const uint32_t b_st = Bs_u + 4u * (lr * GP + kg);                                      \
    const int a_off = ((lane & 7) + ((lane >> 3) & 1) * 8) * GP + ((lane >> 4) & 1) * 4;   \
    const int b_off = ((lane & 7) + ((lane >> 4) & 1) * 8) * GP + ((lane >> 3) & 1) * 4;   \
    float acc[4][4][4];                                                                    \
    _Pragma("unroll") for (int i = 0; i < 4; i++)                                          \
    _Pragma("unroll") for (int j = 0; j < 4; j++)                                          \
    _Pragma("unroll") for (int r = 0; r < 4; r++) acc[i][j][r] = 0.f;                      \
    const float* Abase = A + (size_t)(m0 + lr) * K + kg;                                   \
    const float* Bbase = (BSEL) + (size_t)((NBASE) + lr) * K + kg;                         \
    const int nk = K / 16;                                                                 \
    _Pragma("unroll") for (int s = 0; s < 2; s++) {                                        \
        cp16(a_st + s * SBYTES,      Abase + s * 16);                                      \
        cp16(a_st + s * SBYTES + 16, Abase + s * 16 + 4);                                  \
        cp16(b_st + s * SBYTES,      Bbase + s * 16);                                      \
        cp16(b_st + s * SBYTES + 16, Bbase + s * 16 + 4);                                  \
        cp_commit();                                                                       \
    }                                                                                      \
    for (int it = 0; it < nk; it++) {                                                      \
        cp_wait1();                                                                        \
        __syncthreads();                                                                   \
        if (it + 2 < nk) {                                                                 \
            const int buf = (it + 2) % 3;                                                  \
            cp16(a_st + buf * SBYTES,      Abase + (it + 2) * 16);                         \
            cp16(a_st + buf * SBYTES + 16, Abase + (it + 2) * 16 + 4);                     \
            cp16(b_st + buf * SBYTES,      Bbase + (it + 2) * 16);                         \
            cp16(b_st + buf * SBYTES + 16, Bbase + (it + 2) * 16 + 4);                     \
        }                                                                                  \
        cp_commit();                                                                       \
        const int cur = it % 3;                                                            \
        const uint32_t abuf = As_u + (uint32_t)cur * SBYTES;                               \
        const uint32_t bbuf = Bs_u + (uint32_t)cur * SBYTES;                               \
        uint32_t af[2][4][4], bf[2][2][4];                                                 \
        _Pragma("unroll") for (int ks2 = 0; ks2 < 2; ks2++) {                              \
            _Pragma("unroll") for (int mf = 0; mf < 4; mf++)                               \
                ldm_x4(af[ks2][mf], abuf + 4u * ((wm + mf * 16) * GP + ks2 * 8 + a_off));  \
            _Pragma("unroll") for (int np = 0; np < 2; np++)                               \
                ldm_x4(bf[ks2][np], bbuf + 4u * ((wn + np * 16) * GP + ks2 * 8 + b_off));  \
        }                                                                                  \
        _Pragma("unroll") for (int ks2 = 0; ks2 < 2; ks2++)                                \
        _Pragma("unroll") for (int mf = 0; mf < 4; mf++)                                   \
        _Pragma("unroll") for (int np = 0; np < 2; np++) {                                 \
            mma_tf32(acc[mf][np * 2],     af[ks2][mf], bf[ks2][np]);                       \
            mma_tf32(acc[mf][np * 2 + 1], af[ks2][mf], bf[ks2][np] + 2);                   \
        }                                                                                  \
    }

__global__ __launch_bounds__(256, 2) void gemm_tf32_nt(
    const float* __restrict__ A, const float* __restrict__ B,
    float* __restrict__ C, int M, int N, int K)
{
    GEMM_MAIN(B, blockIdx.x * 128)
    const int n0 = blockIdx.x * 128;
#pragma unroll
    for (int mf = 0; mf < 4; mf++)
#pragma unroll
        for (int nf = 0; nf < 4; nf++) {
            const int row = m0 + wm + mf * 16 + (lane >> 2);
            const int col = n0 + wn + nf * 8 + (lane & 3) * 2;
            *(float2*)(C + (size_t)row * N + col)       = make_float2(acc[mf][nf][0], acc[mf][nf][1]);
            *(float2*)(C + (size_t)(row + 8) * N + col) = make_float2(acc[mf][nf][2], acc[mf][nf][3]);
        }
}

// QKV GEMM: q/k blocks -> g_qkv rows (tf32-rounded); v blocks -> g_vt TRANSPOSED.
__global__ __launch_bounds__(256, 2) void gemm_qkv(
    const float* __restrict__ A, const float* __restrict__ Wq,
    const float* __restrict__ Wk, const float* __restrict__ Wv,
    float* __restrict__ C, int M, int K)
{
    const int nblk = blockIdx.x * 128;
    const float* Bsel; int nbase;
    if (nblk < KOFF)      { Bsel = Wq; nbase = nblk; }
    else if (nblk < VOFF) { Bsel = Wk; nbase = nblk - KOFF; }
    else                  { Bsel = Wv; nbase = nblk - VOFF; }
    GEMM_MAIN(Bsel, nbase)
    if (nblk < VOFF) {
#pragma unroll
        for (int mf = 0; mf < 4; mf++)
#pragma unroll
            for (int nf = 0; nf < 4; nf++) {
                const int row = m0 + wm + mf * 16 + (lane >> 2);
                const int col = nblk + wn + nf * 8 + (lane & 3) * 2;
                *(float2*)(C + (size_t)row * QKVD + col) =
                    make_float2(to_tf32(acc[mf][nf][0]), to_tf32(acc[mf][nf][1]));
                *(float2*)(C + (size_t)(row + 8) * QKVD + col) =
                    make_float2(to_tf32(acc[mf][nf][2]), to_tf32(acc[mf][nf][3]));
            }
    } else {
        // V: write transposed g_vt[b][kvh][d][t]
#pragma unroll
        for (int mf = 0; mf < 4; mf++)
#pragma unroll
            for (int nf = 0; nf < 4; nf++) {
                const int row = m0 + wm + mf * 16 + (lane >> 2);   // token index
                const int col = (nbase) + wn + nf * 8 + (lane & 3) * 2;  // v feature 0..255
                const int kvh = col >> 6, d = col & 63;
                const int b = row >> 11, tok = row & 2047;
                float* base = g_vt + ((size_t)((b * HKV_ + kvh) * HD_ + d)) * T_ + tok;
                base[0]      = to_tf32(acc[mf][nf][0]);   // (d,   tok)
                base[T_]     = to_tf32(acc[mf][nf][1]);   // (d+1, tok)
                base[8]      = to_tf32(acc[mf][nf][2]);   // (d,   tok+8)
                base[T_ + 8] = to_tf32(acc[mf][nf][3]);   // (d+1, tok+8)
            }
    }
}

// ---------------------------------------------------------------------------
// RoPE in-place on g_qkv (q and k only); q scaled by q_gain[h]/sqrt(HD).
// ---------------------------------------------------------------------------
__global__ void rope_kernel(const float* __restrict__ q_gain)
{
    const int total_q = B_ * T_ * H_ * (HD_ / 2);
    const int total_k = B_ * T_ * HKV_ * (HD_ / 2);
    int idx = blockIdx.x * blockDim.x + threadIdx.x;
    if (idx >= total_q + total_k) return;

    const float LN = logf(10000.0f);
    if (idx < total_q) {
        int j = idx & 31;
        int h = (idx >> 5) & 15;
        int t = (idx >> 9) & 2047;
        int b = idx >> 20;
        float invf = expf(-LN * ((float)(2 * j) / (float)HD_));
        float f = (float)t * invf;
        float c = cosf(f), s = sinf(f);
        float* base = g_qkv + ((size_t)(b * T_ + t)) * QKVD + h * HD_;
        float x1 = base[j], x2 = base[j + 32];
        float gain = q_gain[h] * 0.125f;
        base[j]      = to_tf32((x1 * c - x2 * s) * gain);
        base[j + 32] = to_tf32((x1 * s + x2 * c) * gain);
    } else {
        int i2 = idx - total_q;
        int j  = i2 & 31;
        int kv = (i2 >> 5) & 3;
        int t  = (i2 >> 7) & 2047;
        int b  = i2 >> 18;
        float invf = expf(-LN * ((float)(2 * j) / (float)HD_));
        float f = (float)t * invf;
        float c = cosf(f), s = sinf(f);
        float* base = g_qkv + ((size_t)(b * T_ + t)) * QKVD + KOFF + kv * HD_;
        float x1 = base[j], x2 = base[j + 32];
        base[j]      = to_tf32(x1 * c - x2 * s);
        base[j + 32] = to_tf32(x1 * s + x2 * c);
    }
}

// ---------------------------------------------------------------------------
// Tensor-core flash attention (causal, GQA) with cp.async double-buffered
// K and V^T tiles. Pitch 68 (17x16B, odd) -> conflict-free ldmatrix phases.
// ---------------------------------------------------------------------------
#define FP2 68
#define TILEB (64 * FP2 * 4)
#define FLASH_SMEM ((2 * 64 + 2 * 64 + 128) * FP2 * 4)   // 104448 B

__global__ __launch_bounds__(256, 2) void flash_tc()
{
    extern __shared__ float sm[];
    float* Ks = sm;                      // [2][64 s][FP2] (cols = d)
    float* Vt = sm + 2 * 64 * FP2;       // [2][64 d][FP2] (cols = s)
    float* Ps = sm + 4 * 64 * FP2;       // [128 q][FP2]   (cols = s)

    const int qt   = (int)gridDim.x - 1 - (int)blockIdx.x;  // heavy blocks first
    const int h    = blockIdx.y;
    const int b    = blockIdx.z;
    const int tid  = threadIdx.x;
    const int lane = tid & 31;
    const int wid  = tid >> 5;
    const int wm   = wid * 16;
    const int kvh  = h >> 2;
    const int r0   = lane >> 2;
    const int c0   = lane & 3;

    const uint32_t Ks_u = smem_u32(Ks);
    const uint32_t Vt_u = smem_u32(Vt);
    const uint32_t Ps_u = smem_u32(Ps);

    const int kf_off = (lane & 7) * FP2 + (lane >> 3) * 4;   // K/V B-frag
    const int pa_off = ((lane & 7) + ((lane >> 3) & 1) * 8) * FP2 + ((lane >> 4) & 1) * 4;

    // cp.async tile loaders: thread -> (row = tid>>2, 16-float col group = tid&3)
    const int ld_r = tid >> 2;
    const int ld_c = (tid & 3) * 16;
    const float* kgbase = g_qkv + ((size_t)(b * T_ + ld_r)) * QKVD + KOFF + kvh * HD_ + ld_c;
    const float* vgbase = g_vt + ((size_t)((b * HKV_ + kvh) * HD_ + ld_r)) * T_ + ld_c;
    const uint32_t ks_dst = Ks_u + 4u * (ld_r * FP2 + ld_c);
    const uint32_t vt_dst = Vt_u + 4u * (ld_r * FP2 + ld_c);

#define ISSUE_TILE(S0, BUF)                                                   \
    {                                                                         \
        const float* kg = kgbase + (size_t)(S0) * QKVD;                       \
        const float* vg = vgbase + (S0);                                      \
        _Pragma("unroll") for (int u = 0; u < 4; u++) {                       \
            cp16(ks_dst + (BUF) * TILEB + 16 * u, kg + 4 * u);                \
            cp16(vt_dst + (BUF) * TILEB + 16 * u, vg + 4 * u);                \
        }                                                                     \
    }

    // Q fragments in registers (already tf32)
    uint32_t qf[8][4];
    {
        const float* q0 = g_qkv + ((size_t)(b * T_ + qt * 128 + wm + r0)) * QKVD + h * HD_;
        const float* q1 = q0 + (size_t)8 * QKVD;
#pragma unroll
        for (int kb = 0; kb < 8; kb++) {
            qf[kb][0] = __float_as_uint(q0[kb * 8 + c0]);
            qf[kb][1] = __float_as_uint(q1[kb * 8 + c0]);
            qf[kb][2] = __float_as_uint(q0[kb * 8 + c0 + 4]);
            qf[kb][3] = __float_as_uint(q1[kb * 8 + c0 + 4]);
        }
    }

    float oacc[8][4];
#pragma unroll
    for (int nf = 0; nf < 8; nf++)
#pragma unroll
        for (int r = 0; r < 4; r++) oacc[nf][r] = 0.f;
    float m0v = -1e30f, m1v = -1e30f, l0 = 0.f, l1 = 0.f;

    const int qi0 = qt * 128 + wm + r0;
    const int qi1 = qi0 + 8;
    const int ntiles = (qt + 1) * 2;

    // prologue: prefetch tiles 0 and 1
    ISSUE_TILE(0, 0); cp_commit();
    ISSUE_TILE(64, 1); cp_commit();

    for (int it = 0; it < ntiles; it++) {
        const int s0 = it * 64;
        cp_wait1();
        __syncthreads();
        const uint32_t ksb = Ks_u + (uint32_t)(it & 1) * TILEB;
        const uint32_t vtb = Vt_u + (uint32_t)(it & 1) * TILEB;

        if (s0 <= qt * 128 + wm + 15) {
            // S = Q @ K^T (per-warp 16x64)
            float sacc[8][4];
#pragma unroll
            for (int nf = 0; nf < 8; nf++)
#pragma unroll
                for (int r = 0; r < 4; r++) sacc[nf][r] = 0.f;

#pragma unroll
            for (int kbp = 0; kbp < 4; kbp++) {
#pragma unroll
                for (int nf = 0; nf < 8; nf++) {
                    uint32_t kb4[4];
                    ldm_x4(kb4, ksb + 4u * (nf * 8 * FP2 + kbp * 16 + kf_off));
                    mma_tf32(sacc[nf], qf[2 * kbp],     kb4);
                    mma_tf32(sacc[nf], qf[2 * kbp + 1], kb4 + 2);
                }
            }

            if (s0 + 63 > qt * 128 + wm) {
#pragma unroll
                for (int nf = 0; nf < 8; nf++) {
                    int sj = s0 + nf * 8 + 2 * c0;
                    if (sj > qi0)     sacc[nf][0] = -1e30f;
                    if (sj + 1 > qi0) sacc[nf][1] = -1e30f;
                    if (sj > qi1)     sacc[nf][2] = -1e30f;
                    if (sj + 1 > qi1) sacc[nf][3] = -1e30f;
                }
            }

            float tm0 = -1e30f, tm1 = -1e30f;
#pragma unroll
            for (int nf = 0; nf < 8; nf++) {
                tm0 = fmaxf(tm0, fmaxf(sacc[nf][0], sacc[nf][1]));
                tm1 = fmaxf(tm1, fmaxf(sacc[nf][2], sacc[nf][3]));
            }
            tm0 = fmaxf(tm0, __shfl_xor_sync(0xffffffff, tm0, 1));
            tm0 = fmaxf(tm0, __shfl_xor_sync(0xffffffff, tm0, 2));
            tm1 = fmaxf(tm1, __shfl_xor_sync(0xffffffff, tm1, 1));
            tm1 = fmaxf(tm1, __shfl_xor_sync(0xffffffff, tm1, 2));

            float mn0 = fmaxf(m0v, tm0), mn1 = fmaxf(m1v, tm1);
            float cor0 = __expf(m0v - mn0), cor1 = __expf(m1v - mn1);

            float ps0 = 0.f, ps1 = 0.f;
#pragma unroll
            for (int nf = 0; nf < 8; nf++) {
                float p0 = to_tf32(__expf(sacc[nf][0] - mn0));
                float p1 = to_tf32(__expf(sacc[nf][1] - mn0));
                float p2 = to_tf32(__expf(sacc[nf][2] - mn1));
                float p3 = to_tf32(__expf(sacc[nf][3] - mn1));
                ps0 += p0 + p1; ps1 += p2 + p3;
                *(float2*)&Ps[(wm + r0)     * FP2 + nf * 8 + 2 * c0] = make_float2(p0, p1);
                *(float2*)&Ps[(wm + r0 + 8) * FP2 + nf * 8 + 2 * c0] = make_float2(p2, p3);
            }
            ps0 += __shfl_xor_sync(0xffffffff, ps0, 1);
            ps0 += __shfl_xor_sync(0xffffffff, ps0, 2);
            ps1 += __shfl_xor_sync(0xffffffff, ps1, 1);
            ps1 += __shfl_xor_sync(0xffffffff, ps1, 2);
            l0 = l0 * cor0 + ps0;
            l1 = l1 * cor1 + ps1;

#pragma unroll
            for (int nf = 0; nf < 8; nf++) {
                oacc[nf][0] *= cor0; oacc[nf][1] *= cor0;
                oacc[nf][2] *= cor1; oacc[nf][3] *= cor1;
            }
            m0v = mn0; m1v = mn1;

            __syncwarp();

            // O += P @ V  (V^T tile, same B-frag pattern as K)
#pragma unroll
            for (int kbp = 0; kbp < 4; kbp++) {
                uint32_t pa0[4], pa1[4];
                ldm_x4(pa0, Ps_u + 4u * (wm * FP2 + (2 * kbp)     * 8 + pa_off));
                ldm_x4(pa1, Ps_u + 4u * (wm * FP2 + (2 * kbp + 1) * 8 + pa_off));
#pragma unroll
                for (int nf = 0; nf < 8; nf++) {
                    uint32_t vb[4];
                    ldm_x4(vb, vtb + 4u * (nf * 8 * FP2 + kbp * 16 + kf_off));
                    mma_tf32(oacc[nf], pa0, vb);
                    mma_tf32(oacc[nf], pa1, vb + 2);
                }
            }
        }
        __syncthreads();
        if (it + 2 < ntiles) ISSUE_TILE(s0 + 128, it & 1);
        cp_commit();
    }

    // epilogue: normalize, tf32-round (proj GEMM consumes this), write O
    float il0 = 1.0f / l0, il1 = 1.0f / l1;
    float* o0 = g_o + ((size_t)(b * T_ + qi0)) * D_ + h * HD_;
    float* o1 = g_o + ((size_t)(b * T_ + qi1)) * D_ + h * HD_;
#pragma unroll
    for (int nf = 0; nf < 8; nf++) {
        *(float2*)(o0 + nf * 8 + 2 * c0) = make_float2(to_tf32(oacc[nf][0] * il0), to_tf32(oacc[nf][1] * il0));
        *(float2*)(o1 + nf * 8 + 2 * c0) = make_float2(to_tf32(oacc[nf][2] * il1), to_tf32(oacc[nf][3] * il1));
    }
}

// ---------------------------------------------------------------------------
// Launch
// ---------------------------------------------------------------------------
extern "C" void kernel_launch(void* const* d_in, const int* in_sizes, int n_in,
                              void* d_out, int out_size)
{
    (void)in_sizes; (void)n_in; (void)out_size;
    const float* x      = (const float*)d_in[0];
    const float* Wq     = (const float*)d_in[1];
    const float* Wk     = (const float*)d_in[2];
    const float* Wv     = (const float*)d_in[3];
    const float* Wp     = (const float*)d_in[4];
    const float* q_gain = (const float*)d_in[5];
    float* out = (float*)d_out;

    float *qkvb, *ob, *pre;
    cudaGetSymbolAddress((void**)&qkvb, g_qkv);
    cudaGetSymbolAddress((void**)&ob, g_o);
    cudaGetSymbolAddress((void**)&pre, g_pre);

    cudaFuncSetAttribute(flash_tc, cudaFuncAttributeMaxDynamicSharedMemorySize, FLASH_SMEM);

    const int M = B_ * T_;   // 4096

    preround_kernel<<<(PRE_TOTAL / 4 + 255) / 256, 256>>>(x, Wq, Wk, Wv, Wp);

    gemm_qkv<<<dim3(QKVD / 128, M / 128), 256>>>(
        pre + PRE_X, pre + PRE_WQ, pre + PRE_WK, pre + PRE_WV, qkvb, M, D_);

    const int total = B_ * T_ * (H_ + HKV_) * (HD_ / 2);
    rope_kernel<<<(total + 255) / 256, 256>>>(q_gain);

    flash_tc<<<dim3(T_ / 128, H_, B_), 256, FLASH_SMEM>>>();

    gemm_tf32_nt<<<dim3(D_ / 128, M / 128), 256>>>(ob, pre + PRE_WP, out, M, D_, D_);
}